// round 14
// baseline (speedup 1.0000x reference)
#include <cuda_runtime.h>
#include <cuda_bf16.h>
#include <math.h>
#include <stdint.h>

#define T_LEN 1016
#define TB 8
#define NTAIL 127
#define XSZ 65024

// ---------------- scratch layout (float units) -------------------------------------
constexpr size_t OFF_WC_HI  = 0;
constexpr size_t OFF_WC_LO  = OFF_WC_HI  + 2097152;
constexpr size_t OFF_FT_HI  = OFF_WC_LO  + 2097152;
constexpr size_t OFF_FT_LO  = OFF_FT_HI  + 131072;
constexpr size_t OFF_BR_HI  = OFF_FT_LO  + 131072;
constexpr size_t OFF_BR_LO  = OFF_BR_HI  + 1048576;
constexpr size_t OFF_B2_HI  = OFF_BR_LO  + 1048576;
constexpr size_t OFF_B2_LO  = OFF_B2_HI  + 1048576;
constexpr size_t OFF_CACTS  = OFF_B2_LO  + 1048576;
constexpr size_t OFF_WOT    = OFF_CACTS  + 2080768;
constexpr size_t OFF_WET    = OFF_WOT    + 65536;
constexpr size_t OFF_XB     = OFF_WET    + 65536;                 // 2 x buffers
constexpr size_t OFF_WSKT   = OFF_XB     + 2 * (size_t)XSZ;
constexpr size_t OFF_WRST   = OFF_WSKT   + 262144;
constexpr size_t OFF_WDT    = OFF_WRST   + 61440;                 // [l][j][c] float2
constexpr size_t SCRATCH_SZ = OFF_WDT + 262144;

__device__ __align__(1024) float g_scratch[SCRATCH_SZ];
__device__ unsigned g_bar;
__device__ unsigned g_cnt1[8];
__device__ unsigned g_cnt2[16];

// ---------------- PTX helpers -------------------------------------------------------
__device__ __forceinline__ uint32_t s2u(const void* p) {
    uint32_t a;
    asm("{ .reg .u64 t; cvta.to.shared.u64 t, %1; cvt.u32.u64 %0, t; }" : "=r"(a) : "l"(p));
    return a;
}
__device__ __forceinline__ void cp16(uint32_t dst, const void* src) {
    asm volatile("cp.async.cg.shared.global [%0], [%1], 16;" :: "r"(dst), "l"(src));
}
#define CP_COMMIT() asm volatile("cp.async.commit_group;" ::: "memory")

__device__ __forceinline__ void ldsm4(uint32_t* r, uint32_t a) {
    asm volatile("ldmatrix.sync.aligned.m8n8.x4.shared.b16 {%0,%1,%2,%3}, [%4];"
                 : "=r"(r[0]), "=r"(r[1]), "=r"(r[2]), "=r"(r[3]) : "r"(a));
}
__device__ __forceinline__ void ldsm4t(uint32_t* r, uint32_t a) {
    asm volatile("ldmatrix.sync.aligned.m8n8.x4.trans.shared.b16 {%0,%1,%2,%3}, [%4];"
                 : "=r"(r[0]), "=r"(r[1]), "=r"(r[2]), "=r"(r[3]) : "r"(a));
}
__device__ __forceinline__ void mma_bf16(float* c, const uint32_t* a, const uint32_t* b) {
    asm volatile("mma.sync.aligned.m16n8k16.row.col.f32.bf16.bf16.f32 "
                 "{%0,%1,%2,%3}, {%4,%5,%6,%7}, {%8,%9}, {%0,%1,%2,%3};"
                 : "+f"(c[0]), "+f"(c[1]), "+f"(c[2]), "+f"(c[3])
                 : "r"(a[0]), "r"(a[1]), "r"(a[2]), "r"(a[3]), "r"(b[0]), "r"(b[1]));
}

__device__ __forceinline__ uint32_t off_km64(int row, int kk) {
    return (uint32_t)(row * 128 + ((kk ^ (row & 7)) << 4));
}
__device__ __forceinline__ uint32_t off_tr64(int k, int mc) {
    return (uint32_t)(k * 256 + ((mc ^ (k & 7)) << 4));
}
__device__ __forceinline__ uint32_t bpack(float x, float y) {
    uint32_t lo = (uint32_t)__bfloat16_as_ushort(__float2bfloat16(x));
    uint32_t hi = (uint32_t)__bfloat16_as_ushort(__float2bfloat16(y));
    return lo | (hi << 16);
}
__device__ __forceinline__ unsigned ldacq(const unsigned* p) {
    unsigned v;
    asm volatile("ld.acquire.gpu.global.u32 %0, [%1];" : "=r"(v) : "l"(p) : "memory");
    return v;
}

// ---------------- prep mega-kernel ---------------------------------------------------
__global__ __launch_bounds__(256)
void k_prep(const float* __restrict__ features, const float* __restrict__ w_cond,
            const float* __restrict__ w_out, const float* __restrict__ w_end,
            const float* __restrict__ w_skip, const float* __restrict__ w_res,
            const float* __restrict__ w_dil)
{
    __shared__ float tile[32 * 33 * 2];
    float2* tile2 = reinterpret_cast<float2*>(tile);
    const int b = blockIdx.x, tid = threadIdx.x;
    const int x = tid & 31, y = tid >> 5;

    __nv_bfloat16* WC_HI = (__nv_bfloat16*)(g_scratch + OFF_WC_HI);
    __nv_bfloat16* WC_LO = (__nv_bfloat16*)(g_scratch + OFF_WC_LO);
    __nv_bfloat16* FT_HI = (__nv_bfloat16*)(g_scratch + OFF_FT_HI);
    __nv_bfloat16* FT_LO = (__nv_bfloat16*)(g_scratch + OFF_FT_LO);

    auto tr = [&](const float* ip, float* op, int R, int C, int c0, int r0) {
#pragma unroll
        for (int i = 0; i < 32; i += 8)
            tile[(y + i) * 33 + x] = ip[(size_t)(r0 + y + i) * C + c0 + x];
        __syncthreads();
#pragma unroll
        for (int i = 0; i < 32; i += 8)
            op[(size_t)(c0 + y + i) * R + r0 + x] = tile[x * 33 + y + i];
    };

    if (b < 4096) {
        int i = b * 256 + tid;
        float4 v = reinterpret_cast<const float4*>(w_cond)[i];
        __nv_bfloat16 h0 = __float2bfloat16(v.x), h1 = __float2bfloat16(v.y);
        __nv_bfloat16 h2 = __float2bfloat16(v.z), h3 = __float2bfloat16(v.w);
        uint2 vh = make_uint2(
            (uint32_t)__bfloat16_as_ushort(h0) | ((uint32_t)__bfloat16_as_ushort(h1) << 16),
            (uint32_t)__bfloat16_as_ushort(h2) | ((uint32_t)__bfloat16_as_ushort(h3) << 16));
        uint2 vl = make_uint2(bpack(v.x - __bfloat162float(h0), v.y - __bfloat162float(h1)),
                              bpack(v.z - __bfloat162float(h2), v.w - __bfloat162float(h3)));
        reinterpret_cast<uint2*>(WC_HI)[i] = vh;
        reinterpret_cast<uint2*>(WC_LO)[i] = vl;
    } else if (b < 4352) {
        int t = b - 4096;
        int c0 = (t & 3) * 32, r0 = (t >> 2) * 32;
#pragma unroll
        for (int i = 0; i < 32; i += 8)
            tile[(y + i) * 33 + x] = features[(size_t)(r0 + y + i) * 128 + c0 + x];
        __syncthreads();
#pragma unroll
        for (int i = 0; i < 32; i += 8) {
            float v = tile[x * 33 + y + i];
            size_t o = (size_t)(c0 + y + i) * 2048 + r0 + x;
            __nv_bfloat16 h = __float2bfloat16(v);
            FT_HI[o] = h;
            FT_LO[o] = __float2bfloat16(v - __bfloat162float(h));
        }
    } else if (b < 4416) {
        int t = b - 4352;
        tr(w_out, g_scratch + OFF_WOT, 256, 256, (t & 7) * 32, (t >> 3) * 32);
    } else if (b < 4480) {
        int t = b - 4416;
        tr(w_end, g_scratch + OFF_WET, 256, 256, (t & 7) * 32, (t >> 3) * 32);
    } else if (b < 4736) {
        int t = b - 4480;
        int l = t >> 4, bx = t & 1, by = (t >> 1) & 7;
        tr(w_skip + (size_t)l * 16384, g_scratch + OFF_WSKT + (size_t)l * 16384,
           256, 64, bx * 32, by * 32);
    } else if (b < 4796) {
        int t = b - 4736;
        int l = t >> 2, bx = t & 1, by = (t >> 1) & 1;
        tr(w_res + (size_t)l * 4096, g_scratch + OFF_WRST + (size_t)l * 4096,
           64, 64, bx * 32, by * 32);
    } else if (b < 4924) {
        int t = b - 4796;
        int l = t >> 3, sub = t & 7;
        int r0 = (sub >> 1) * 32;               // c dim
        int c0 = (sub & 1) * 32;                // j dim
        const float2* ip2 = reinterpret_cast<const float2*>(w_dil + (size_t)l * 16384);
        float2* op2 = reinterpret_cast<float2*>(g_scratch + OFF_WDT) + (size_t)l * 8192;
#pragma unroll
        for (int i = 0; i < 32; i += 8)
            tile2[(y + i) * 33 + x] = ip2[(size_t)(r0 + y + i) * 64 + c0 + x];
        __syncthreads();
#pragma unroll
        for (int i = 0; i < 32; i += 8)
            op2[(size_t)(c0 + y + i) * 128 + r0 + x] = tile2[x * 33 + y + i];
    } else {
        if (tid < 8)  g_cnt1[tid] = 0u;
        if (tid < 16) g_cnt2[tid] = 0u;
        if (tid == 0) g_bar = 0u;
    }
}

// ---------------- GEMM core (bf16 A + bf16 B, K64 3-stage pipeline, 512 thr) --------
__device__ __forceinline__ void gemm_core(
    char* smem, uint32_t sb, int tid,
    const __nv_bfloat16* __restrict__ Ahi, const __nv_bfloat16* __restrict__ Alo,
    const __nv_bfloat16* __restrict__ Bhi, const __nv_bfloat16* __restrict__ Blo,
    int K, int bm, int bn, int mode, const float* __restrict__ bias,
    float* __restrict__ outF,
    __nv_bfloat16* __restrict__ outHi, __nv_bfloat16* __restrict__ outLo)
{
    const int wid = tid >> 5, lane = tid & 31;
    const int wm = (wid & 3) * 32, wn = (wid >> 2) * 32;
    const uint32_t STG = 65536;

    float acc[2][4][4];
#pragma unroll
    for (int mt = 0; mt < 2; mt++)
#pragma unroll
        for (int nt = 0; nt < 4; nt++)
#pragma unroll
            for (int i = 0; i < 4; i++) acc[mt][nt][i] = 0.0f;

    const int nsteps = K >> 6;

    auto fill_ab = [&](int s, int k0) {
        uint32_t base = sb + (uint32_t)s * STG;
#pragma unroll
        for (int i = 0; i < 2; i++) {
            int idx = tid + i * 512;
            int row = idx >> 3, kk = idx & 7;
            uint32_t d = off_km64(row, kk);
            cp16(base + d,         Ahi + (size_t)(bm + row) * K + k0 + kk * 8);
            cp16(base + 16384 + d, Alo + (size_t)(bm + row) * K + k0 + kk * 8);
            cp16(base + 32768 + d, Bhi + (size_t)(bn + row) * K + k0 + kk * 8);
            cp16(base + 49152 + d, Blo + (size_t)(bn + row) * K + k0 + kk * 8);
        }
    };

    fill_ab(0, 0);  CP_COMMIT();
    fill_ab(1, 64); CP_COMMIT();

    int sc = 0;
    for (int it = 0; it < nsteps; it++) {
        int sn = sc + 1; if (sn == 3) sn = 0;
        int sf = sn + 1; if (sf == 3) sf = 0;

        if (it < nsteps - 1)
            asm volatile("cp.async.wait_group 1;" ::: "memory");
        else
            asm volatile("cp.async.wait_group 0;" ::: "memory");
        __syncthreads();

        if (it + 2 < nsteps) { fill_ab(sf, (it + 2) * 64); CP_COMMIT(); }

        uint32_t base = sb + (uint32_t)sc * STG;
#pragma unroll
        for (int s = 0; s < 4; s++) {
            const int kk0 = s * 2;
            uint32_t af[2][2][4];
#pragma unroll
            for (int mt = 0; mt < 2; mt++) {
                int r2 = wm + mt * 16 + (lane & 15);
                int k2 = kk0 + (lane >> 4);
                uint32_t ad = off_km64(r2, k2);
                ldsm4(af[mt][0], base + ad);
                ldsm4(af[mt][1], base + 16384 + ad);
            }
            uint32_t bh[4][2], bl[4][2];
#pragma unroll
            for (int p = 0; p < 2; p++) {
                int r2 = wn + p * 16 + ((lane >> 4) << 3) + (lane & 7);
                int k2 = kk0 + ((lane >> 3) & 1);
                uint32_t bd = off_km64(r2, k2);
                uint32_t r[4];
                ldsm4(r, base + 32768 + bd);
                bh[2 * p][0] = r[0]; bh[2 * p][1] = r[1];
                bh[2 * p + 1][0] = r[2]; bh[2 * p + 1][1] = r[3];
                ldsm4(r, base + 49152 + bd);
                bl[2 * p][0] = r[0]; bl[2 * p][1] = r[1];
                bl[2 * p + 1][0] = r[2]; bl[2 * p + 1][1] = r[3];
            }
#pragma unroll
            for (int mt = 0; mt < 2; mt++)
#pragma unroll
                for (int nt = 0; nt < 4; nt++) {
                    mma_bf16(acc[mt][nt], af[mt][0], bh[nt]);
                    mma_bf16(acc[mt][nt], af[mt][0], bl[nt]);
                    mma_bf16(acc[mt][nt], af[mt][1], bh[nt]);
                }
        }
        sc = sn;
    }
    __syncthreads();

    float* sd = reinterpret_cast<float*>(smem);
#pragma unroll
    for (int mt = 0; mt < 2; mt++)
#pragma unroll
        for (int nt = 0; nt < 4; nt++) {
            int r = wm + mt * 16 + (lane >> 2);
            int c = wn + nt * 8 + (lane & 3) * 2;
            sd[r * 129 + c]           = acc[mt][nt][0];
            sd[r * 129 + c + 1]       = acc[mt][nt][1];
            sd[(r + 8) * 129 + c]     = acc[mt][nt][2];
            sd[(r + 8) * 129 + c + 1] = acc[mt][nt][3];
        }
    __syncthreads();

    if (mode == 1) {
        int mg = (tid & 31) * 4;
        int nl = tid >> 5;
        for (int n0 = 0; n0 < 128; n0 += 16) {
            int n = n0 + nl;
            uint2 vh, vl;
            __nv_bfloat16* hp = (__nv_bfloat16*)&vh;
            __nv_bfloat16* lp = (__nv_bfloat16*)&vl;
#pragma unroll
            for (int j = 0; j < 4; j++) {
                float v = sd[(mg + j) * 129 + n] + bias[bm + mg + j];
                __nv_bfloat16 h = __float2bfloat16(v);
                hp[j] = h;
                lp[j] = __float2bfloat16(v - __bfloat162float(h));
            }
            *reinterpret_cast<uint2*>(outHi + (size_t)(bn + n) * 2048 + bm + mg) = vh;
            *reinterpret_cast<uint2*>(outLo + (size_t)(bn + n) * 2048 + bm + mg) = vl;
        }
    } else {
        int mo = tid >> 7, n = tid & 127;
        int gn = bn + n;
        if (gn < T_LEN) {
            for (int m0 = 0; m0 < 128; m0 += 4) {
                int m = m0 + mo;
                outF[(size_t)(bm + m) * T_LEN + gn] = sd[m * 129 + n] + bias[bm + m];
            }
        }
    }
}

// ---------------- upsample GEMM: 256 thr, 8 warps, 64x32 warp tiles ------------------
__global__ __launch_bounds__(256)
void k_gemm_up(const float* __restrict__ Af32,
               const __nv_bfloat16* __restrict__ Bhi, const __nv_bfloat16* __restrict__ Blo,
               const float* __restrict__ bias,
               __nv_bfloat16* __restrict__ outHi, __nv_bfloat16* __restrict__ outLo)
{
    extern __shared__ char smem[];
    uint32_t sb = s2u(smem);
    const int tid = threadIdx.x;
    const int wid = tid >> 5, lane = tid & 31;
    const int Mg = 32768, K = 2048;
    const int wm = (wid & 1) * 64, wn = (wid >> 1) * 32;   // 2 x 4 warp grid, 64x32 tiles
    const uint32_t STG = 65536;
    const int nsteps = K >> 6;

    for (int tile = 0; tile < 2; tile++) {
        const int bm = (blockIdx.x + tile * 128) * 128;

        float acc[4][4][4];
#pragma unroll
        for (int mt = 0; mt < 4; mt++)
#pragma unroll
            for (int nt = 0; nt < 4; nt++)
#pragma unroll
                for (int i = 0; i < 4; i++) acc[mt][nt][i] = 0.0f;

        float4 pre[8];

        auto ldg_pre = [&](int k0) {
#pragma unroll
            for (int i = 0; i < 8; i++) {
                int u = tid + i * 256;
                int k = u >> 5, f4 = u & 31;
                pre[i] = *reinterpret_cast<const float4*>(
                    Af32 + (size_t)(k0 + k) * Mg + bm + f4 * 4);
            }
        };
        auto sts_pre = [&](int s) {
#pragma unroll
            for (int i = 0; i < 8; i++) {
                int u = tid + i * 256;
                int k = u >> 5, f4 = u & 31;
                float4 v = pre[i];
                __nv_bfloat16 h0 = __float2bfloat16(v.x), h1 = __float2bfloat16(v.y);
                __nv_bfloat16 h2 = __float2bfloat16(v.z), h3 = __float2bfloat16(v.w);
                uint32_t hi01 = (uint32_t)__bfloat16_as_ushort(h0) |
                                ((uint32_t)__bfloat16_as_ushort(h1) << 16);
                uint32_t hi23 = (uint32_t)__bfloat16_as_ushort(h2) |
                                ((uint32_t)__bfloat16_as_ushort(h3) << 16);
                uint32_t lo01 = bpack(v.x - __bfloat162float(h0), v.y - __bfloat162float(h1));
                uint32_t lo23 = bpack(v.z - __bfloat162float(h2), v.w - __bfloat162float(h3));
                int mc = f4 >> 1, half = f4 & 1;
                uint32_t a = (uint32_t)s * STG + off_tr64(k, mc) + half * 8;
                *reinterpret_cast<uint2*>(smem + a) = make_uint2(hi01, hi23);
                *reinterpret_cast<uint2*>(smem + 16384 + a) = make_uint2(lo01, lo23);
            }
        };
        auto fill_b = [&](int s, int k0) {
            uint32_t base = sb + (uint32_t)s * STG;
#pragma unroll
            for (int i = 0; i < 4; i++) {
                int idx = tid + i * 256;
                int row = idx >> 3, kk = idx & 7;
                uint32_t d = off_km64(row, kk);
                cp16(base + 32768 + d, Bhi + (size_t)row * K + k0 + kk * 8);
                cp16(base + 49152 + d, Blo + (size_t)row * K + k0 + kk * 8);
            }
        };

        ldg_pre(0);
        sts_pre(0);
        ldg_pre(64);
        fill_b(0, 0);  CP_COMMIT();
        fill_b(1, 64); CP_COMMIT();

        int sc = 0;
        for (int it = 0; it < nsteps; it++) {
            int sn = sc + 1; if (sn == 3) sn = 0;
            int sf = sn + 1; if (sf == 3) sf = 0;

            if (it < nsteps - 1)
                asm volatile("cp.async.wait_group 1;" ::: "memory");
            else
                asm volatile("cp.async.wait_group 0;" ::: "memory");
            __syncthreads();

            if (it + 1 < nsteps) sts_pre(sn);
            if (it + 2 < nsteps) {
                ldg_pre((it + 2) * 64);
                fill_b(sf, (it + 2) * 64);
                CP_COMMIT();
            }

            uint32_t base = sb + (uint32_t)sc * STG;
#pragma unroll
            for (int s = 0; s < 4; s++) {
                const int kk0 = s * 2;
                uint32_t af[4][2][4];
#pragma unroll
                for (int mt = 0; mt < 4; mt++) {
                    int k  = s * 16 + ((lane >> 4) << 3) + (lane & 7);
                    int mc = ((wm + mt * 16) >> 3) + ((lane >> 3) & 1);
                    uint32_t ad = off_tr64(k, mc);
                    ldsm4t(af[mt][0], base + ad);
                    ldsm4t(af[mt][1], base + 16384 + ad);
                }
                uint32_t bh[4][2], bl[4][2];
#pragma unroll
                for (int p = 0; p < 2; p++) {
                    int r2 = wn + p * 16 + ((lane >> 4) << 3) + (lane & 7);
                    int k2 = kk0 + ((lane >> 3) & 1);
                    uint32_t bd = off_km64(r2, k2);
                    uint32_t r[4];
                    ldsm4(r, base + 32768 + bd);
                    bh[2 * p][0] = r[0]; bh[2 * p][1] = r[1];
                    bh[2 * p + 1][0] = r[2]; bh[2 * p + 1][1] = r[3];
                    ldsm4(r, base + 49152 + bd);
                    bl[2 * p][0] = r[0]; bl[2 * p][1] = r[1];
                    bl[2 * p + 1][0] = r[2]; bl[2 * p + 1][1] = r[3];
                }
#pragma unroll
                for (int mt = 0; mt < 4; mt++)
#pragma unroll
                    for (int nt = 0; nt < 4; nt++) {
                        mma_bf16(acc[mt][nt], af[mt][0], bh[nt]);
                        mma_bf16(acc[mt][nt], af[mt][0], bl[nt]);
                        mma_bf16(acc[mt][nt], af[mt][1], bh[nt]);
                    }
            }
            sc = sn;
        }
        __syncthreads();

        float* sd = reinterpret_cast<float*>(smem);
#pragma unroll
        for (int mt = 0; mt < 4; mt++)
#pragma unroll
            for (int nt = 0; nt < 4; nt++) {
                int r = wm + mt * 16 + (lane >> 2);
                int c = wn + nt * 8 + (lane & 3) * 2;
                sd[r * 129 + c]           = acc[mt][nt][0];
                sd[r * 129 + c + 1]       = acc[mt][nt][1];
                sd[(r + 8) * 129 + c]     = acc[mt][nt][2];
                sd[(r + 8) * 129 + c + 1] = acc[mt][nt][3];
            }
        __syncthreads();

        int bo = bm >> 4;
        for (int u = tid; u < T_LEN; u += 256) {
            int m = u >> 3, p = u & 7;
            uint4 vh, vl;
            __nv_bfloat16* hp = (__nv_bfloat16*)&vh;
            __nv_bfloat16* lp = (__nv_bfloat16*)&vl;
#pragma unroll
            for (int ol = 0; ol < 8; ol++) {
                float v = sd[(ol * 16 + p + 8) * 129 + m] +
                          sd[(ol * 16 + p) * 129 + m + 1] + bias[bo + ol];
                __nv_bfloat16 h = __float2bfloat16(v);
                hp[ol] = h;
                lp[ol] = __float2bfloat16(v - __bfloat162float(h));
            }
            *reinterpret_cast<uint4*>(outHi + (size_t)u * 2048 + bo) = vh;
            *reinterpret_cast<uint4*>(outLo + (size_t)u * 2048 + bo) = vl;
        }
        __syncthreads();
    }
}

// ---------------- fused: encode/embed + cond1 + cond2 + lock-step tail ---------------
__global__ __launch_bounds__(512)
void k_fused(const float* __restrict__ b_cond,
             const float* __restrict__ audio, const float* __restrict__ embed,
             const float* __restrict__ b_dil_all, const float* __restrict__ b_res_all,
             const float* __restrict__ b_skip_all,
             float* __restrict__ out, int write_q)
{
    extern __shared__ char smem[];
    uint32_t sb = s2u(smem);
    const int tid = threadIdx.x;
    const int b = blockIdx.x;
    const int t0 = b * TB;
    float* XB = g_scratch + OFF_XB;

    // ---- phase 0: encode + embed ----
    if (b < NTAIL) {
        int j = tid >> 3, tt = tid & 7;
        int t = t0 + tt;
        float x = audio[t];
        float xc = fminf(1.0f, fmaxf(-1.0f, x));
        float s  = (xc > 0.0f) ? 1.0f : ((xc < 0.0f) ? -1.0f : 0.0f);
        float num = log1pf(__fmul_rn(255.0f, fabsf(xc)));
        float den = log1pf(255.0f);
        float m = __fdiv_rn(__fmul_rn(s, num), den);
        float v = __fadd_rn(__fmul_rn(__fmul_rn(__fadd_rn(m, 1.0f), 0.5f), 255.0f), 0.5f);
        v = fminf(255.0f, fmaxf(0.0f, v));
        int q = (int)v;
        if (write_q && tid < TB) out[(size_t)256 * T_LEN + t] = (float)q;
        XB[(size_t)j * T_LEN + t0 + tt] = embed[q * 64 + j];
        __threadfence();
        __syncthreads();
        if (tid == 0) atomicAdd(&g_bar, 1u);
    }

    __nv_bfloat16* WC_HI = (__nv_bfloat16*)(g_scratch + OFF_WC_HI);
    __nv_bfloat16* WC_LO = (__nv_bfloat16*)(g_scratch + OFF_WC_LO);
    __nv_bfloat16* BR_HI = (__nv_bfloat16*)(g_scratch + OFF_BR_HI);
    __nv_bfloat16* BR_LO = (__nv_bfloat16*)(g_scratch + OFF_BR_LO);
    __nv_bfloat16* B2_HI = (__nv_bfloat16*)(g_scratch + OFF_B2_HI);
    __nv_bfloat16* B2_LO = (__nv_bfloat16*)(g_scratch + OFF_B2_LO);

    const int bm = (b >> 3) * 128, bn = (b & 7) * 128;

    // ---- phase 1: cond GEMM #1 tile ----
    gemm_core(smem, sb, tid, WC_HI, WC_LO, BR_HI, BR_LO, 2048, bm, bn, 1,
              b_cond, nullptr, B2_HI, B2_LO);
    __syncthreads();
    __threadfence();
    if (tid == 0) {
        atomicAdd(&g_cnt1[b & 7], 1u);
        while (ldacq(&g_cnt1[b & 7]) < 16u) {}
    }
    __syncthreads();

    // ---- phase 2: cond GEMM #2 tile ----
    gemm_core(smem, sb, tid, WC_HI, WC_LO, B2_HI, B2_LO, 2048, bm, bn, 2,
              b_cond, g_scratch + OFF_CACTS, nullptr, nullptr);
    __syncthreads();
    __threadfence();
    if (tid == 0) atomicAdd(&g_cnt2[b >> 3], 1u);

    if (b >= NTAIL) return;

    // ---- phase 3: lock-step tail ----
    float*  smf = reinterpret_cast<float*>(smem);
    float2* WD2 = reinterpret_cast<float2*>(smf);
    float*  WSK = smf + 16384;
    float*  WRS = smf + 32768;
    float*  XS0 = smf + 36864;
    float*  XS1 = XS0 + 512;
    float*  IA  = XS1 + 512;
    float*  ACT = IA + 512;
    float*  HS  = ACT + 512;
    float*  HS2 = HS + 2048;

    __syncthreads();   // smem repurpose safety

    float s_acc[4];
#pragma unroll
    for (int i = 0; i < 4; i++) s_acc[i] = 0.0f;

    const int c   = tid & 127;
    const int th  = tid >> 7;       // 0..3, 2 timesteps each
    const int row = tid & 255;
    const int part = tid >> 8;      // 0..1, 4 timesteps each

    for (int layer = 0; layer < 16; layer++) {
        const int d = 1 << (layer & 7);
        const float* xin  = XB + (size_t)(layer & 1) * XSZ;
        float*       xout = XB + (size_t)((layer + 1) & 1) * XSZ;
        const float* cond = g_scratch + OFF_CACTS + (size_t)layer * 128 * T_LEN;
        const char*  wdl  = (const char*)(g_scratch + OFF_WDT + (size_t)layer * 16384);
        const char*  wskl = (const char*)(g_scratch + OFF_WSKT + (size_t)layer * 16384);
        const char*  wrsl = (const char*)(g_scratch + OFF_WRST + (size_t)layer * 4096);

        // stage all layer weights via cp.async (overlaps barrier wait)
#pragma unroll
        for (int i = 0; i < 8; i++) {
            int ch = tid + i * 512;
            cp16(sb + ch * 16, wdl + ch * 16);
            cp16(sb + 65536 + ch * 16, wskl + ch * 16);
        }
#pragma unroll
        for (int i = 0; i < 2; i++) {
            int ch = tid + i * 512;
            cp16(sb + 131072 + ch * 16, wrsl + ch * 16);
        }
        CP_COMMIT();

        if (tid == 0) {
            unsigned tgt = (unsigned)NTAIL * (unsigned)(layer + 1);
            while (ldacq(&g_bar) < tgt) {}
            while (ldacq(&g_cnt2[layer]) < 8u) {}
        }
        __syncthreads();

        // stage x windows
        {
            int j = tid >> 3, tt = tid & 7;
            int ta = t0 - d + tt;
            XS0[tid] = (ta >= 0) ? __ldcg(&xin[(size_t)j * T_LEN + ta]) : 0.0f;
            XS1[tid] = __ldcg(&xin[(size_t)j * T_LEN + t0 + tt]);
        }
        float bd  = b_dil_all[layer * 128 + c];
        float cv0 = cond[(size_t)c * T_LEN + t0 + th * 2];
        float cv1 = cond[(size_t)c * T_LEN + t0 + th * 2 + 1];
        asm volatile("cp.async.wait_group 0;" ::: "memory");
        __syncthreads();

        // dilated conv: 2 timesteps per thread
        float a0 = 0.0f, a1 = 0.0f;
#pragma unroll 16
        for (int j = 0; j < 64; j++) {
            float2 w  = WD2[j * 128 + c];
            float2 x0 = *reinterpret_cast<const float2*>(&XS0[j * TB + th * 2]);
            float2 x1 = *reinterpret_cast<const float2*>(&XS1[j * TB + th * 2]);
            a0 += w.x * x0.x + w.y * x1.x;
            a1 += w.x * x0.y + w.y * x1.y;
        }
        a0 += bd + cv0;
        a1 += bd + cv1;

        __syncthreads();
        if (c >= 64) {
            IA[(c - 64) * TB + th * 2]     = a0;
            IA[(c - 64) * TB + th * 2 + 1] = a1;
        }
        __syncthreads();
        if (c < 64) {
            float g0 = IA[c * TB + th * 2];
            float g1 = IA[c * TB + th * 2 + 1];
            ACT[c * TB + th * 2]     = tanhf(a0) * (1.0f / (1.0f + expf(-g0)));
            ACT[c * TB + th * 2 + 1] = tanhf(a1) * (1.0f / (1.0f + expf(-g1)));
        }
        __syncthreads();

        // residual (1 timestep per thread), then arrive
        if (layer < 15) {
            int c2 = tid & 63, qq = tid >> 6;
            float r = 0.0f;
#pragma unroll 8
            for (int k = 0; k < 64; k++)
                r += WRS[k * 64 + c2] * ACT[k * TB + qq];
            float br = b_res_all[layer * 64 + c2];
            int t = t0 + qq;
            xout[(size_t)c2 * T_LEN + t] = __ldcg(&xin[(size_t)c2 * T_LEN + t]) + r + br;
            __threadfence();
            __syncthreads();
            if (tid == 0) atomicAdd(&g_bar, 1u);
        }

        // skip accumulation (4 timesteps per thread) from smem weights
        {
#pragma unroll 8
            for (int k = 0; k < 64; k++) {
                float w = WSK[k * 256 + row];
                float4 a = *reinterpret_cast<const float4*>(&ACT[k * TB + part * 4]);
                s_acc[0] += w * a.x; s_acc[1] += w * a.y;
                s_acc[2] += w * a.z; s_acc[3] += w * a.w;
            }
            float bs = b_skip_all[layer * 256 + row];
#pragma unroll
            for (int i = 0; i < 4; i++) s_acc[i] += bs;
        }
    }

    // ---- heads ----
    {
        __syncthreads();
#pragma unroll
        for (int i = 0; i < 4; i++)
            HS[row * TB + part * 4 + i] = fmaxf(s_acc[i], 0.0f);
        __syncthreads();

        const float* wo = g_scratch + OFF_WOT;
        float h[4] = {0.0f, 0.0f, 0.0f, 0.0f};
        for (int cc = 0; cc < 256; cc++) {
            float w = wo[cc * 256 + row];
            float4 v = *reinterpret_cast<const float4*>(&HS[cc * TB + part * 4]);
            h[0] += w * v.x; h[1] += w * v.y; h[2] += w * v.z; h[3] += w * v.w;
        }
#pragma unroll
        for (int i = 0; i < 4; i++)
            HS2[row * TB + part * 4 + i] = fmaxf(h[i], 0.0f);
        __syncthreads();

        const float* we = g_scratch + OFF_WET;
        float h2[4] = {0.0f, 0.0f, 0.0f, 0.0f};
        for (int cc = 0; cc < 256; cc++) {
            float w = we[cc * 256 + row];
            float4 v = *reinterpret_cast<const float4*>(&HS2[cc * TB + part * 4]);
            h2[0] += w * v.x; h2[1] += w * v.y; h2[2] += w * v.z; h2[3] += w * v.w;
        }

        if (b == 0 && part == 0) out[(size_t)row * T_LEN] = 0.0f;
#pragma unroll
        for (int i = 0; i < 4; i++) {
            int t = t0 + part * 4 + i;
            if (t + 1 < T_LEN) out[(size_t)row * T_LEN + t + 1] = h2[i];
        }
    }
}

// ---------------- launch -------------------------------------------------------------
extern "C" void kernel_launch(void* const* d_in, const int* in_sizes, int n_in,
                              void* d_out, int out_size)
{
    const float* features = (const float*)d_in[0];
    const float* audio    = (const float*)d_in[1];
    const float* w_up     = (const float*)d_in[2];
    const float* b_up     = (const float*)d_in[3];
    const float* w_cond   = (const float*)d_in[4];
    const float* b_cond   = (const float*)d_in[5];
    const float* embed    = (const float*)d_in[6];
    const float* w_dil    = (const float*)d_in[7];
    const float* b_dil    = (const float*)d_in[8];
    const float* w_res    = (const float*)d_in[9];
    const float* b_res    = (const float*)d_in[10];
    const float* w_skip   = (const float*)d_in[11];
    const float* b_skip   = (const float*)d_in[12];
    const float* w_out    = (const float*)d_in[13];
    const float* w_end    = (const float*)d_in[14];
    float* out = (float*)d_out;

    float* scr = nullptr;
    cudaGetSymbolAddress((void**)&scr, g_scratch);

    __nv_bfloat16* FT_HI = (__nv_bfloat16*)(scr + OFF_FT_HI);
    __nv_bfloat16* FT_LO = (__nv_bfloat16*)(scr + OFF_FT_LO);
    __nv_bfloat16* BR_HI = (__nv_bfloat16*)(scr + OFF_BR_HI);
    __nv_bfloat16* BR_LO = (__nv_bfloat16*)(scr + OFF_BR_LO);

    cudaFuncSetAttribute(k_gemm_up, cudaFuncAttributeMaxDynamicSharedMemorySize, 196608);
    cudaFuncSetAttribute(k_fused,   cudaFuncAttributeMaxDynamicSharedMemorySize, 196608);

    int write_q = (out_size >= 256 * T_LEN + T_LEN) ? 1 : 0;

    // [1] prep
    k_prep<<<4925, 256>>>(features, w_cond, w_out, w_end, w_skip, w_res, w_dil);
    // [2] upsample GEMM (256 thr, 8 warps, 64x32 warp tiles, 2 tiles/block)
    k_gemm_up<<<128, 256, 196608>>>(w_up, FT_HI, FT_LO, b_up, BR_HI, BR_LO);
    // [3] fused encode/embed + cond1 + cond2 + tail
    k_fused<<<128, 512, 196608>>>(b_cond, audio, embed, b_dil, b_res, b_skip,
                                  out, write_q);
}

// round 15
// speedup vs baseline: 1.0051x; 1.0051x over previous
#include <cuda_runtime.h>
#include <cuda_bf16.h>
#include <math.h>
#include <stdint.h>

#define T_LEN 1016
#define TB 8
#define NTAIL 127
#define XSZ 65024

// ---------------- scratch layout (float units) -------------------------------------
constexpr size_t OFF_WC_HI  = 0;
constexpr size_t OFF_WC_LO  = OFF_WC_HI  + 2097152;
constexpr size_t OFF_FT_HI  = OFF_WC_LO  + 2097152;
constexpr size_t OFF_FT_LO  = OFF_FT_HI  + 131072;
constexpr size_t OFF_BR_HI  = OFF_FT_LO  + 131072;
constexpr size_t OFF_BR_LO  = OFF_BR_HI  + 1048576;
constexpr size_t OFF_B2_HI  = OFF_BR_LO  + 1048576;
constexpr size_t OFF_B2_LO  = OFF_B2_HI  + 1048576;
constexpr size_t OFF_CACTS  = OFF_B2_LO  + 1048576;
constexpr size_t OFF_WOT    = OFF_CACTS  + 2080768;
constexpr size_t OFF_WET    = OFF_WOT    + 65536;
constexpr size_t OFF_XB     = OFF_WET    + 65536;                 // 2 x buffers
constexpr size_t OFF_WSKT   = OFF_XB     + 2 * (size_t)XSZ;
constexpr size_t OFF_WRST   = OFF_WSKT   + 262144;
constexpr size_t OFF_WDT    = OFF_WRST   + 61440;                 // [l][j][c] float2
constexpr size_t SCRATCH_SZ = OFF_WDT + 262144;

__device__ __align__(1024) float g_scratch[SCRATCH_SZ];
__device__ unsigned g_bar;
__device__ unsigned g_cnt1[8];
__device__ unsigned g_cnt2[16];

// ---------------- PTX helpers -------------------------------------------------------
__device__ __forceinline__ uint32_t s2u(const void* p) {
    uint32_t a;
    asm("{ .reg .u64 t; cvta.to.shared.u64 t, %1; cvt.u32.u64 %0, t; }" : "=r"(a) : "l"(p));
    return a;
}
__device__ __forceinline__ void cp16(uint32_t dst, const void* src) {
    asm volatile("cp.async.cg.shared.global [%0], [%1], 16;" :: "r"(dst), "l"(src));
}
#define CP_COMMIT() asm volatile("cp.async.commit_group;" ::: "memory")

__device__ __forceinline__ void ldsm4(uint32_t* r, uint32_t a) {
    asm volatile("ldmatrix.sync.aligned.m8n8.x4.shared.b16 {%0,%1,%2,%3}, [%4];"
                 : "=r"(r[0]), "=r"(r[1]), "=r"(r[2]), "=r"(r[3]) : "r"(a));
}
__device__ __forceinline__ void ldsm4t(uint32_t* r, uint32_t a) {
    asm volatile("ldmatrix.sync.aligned.m8n8.x4.trans.shared.b16 {%0,%1,%2,%3}, [%4];"
                 : "=r"(r[0]), "=r"(r[1]), "=r"(r[2]), "=r"(r[3]) : "r"(a));
}
__device__ __forceinline__ void mma_bf16(float* c, const uint32_t* a, const uint32_t* b) {
    asm volatile("mma.sync.aligned.m16n8k16.row.col.f32.bf16.bf16.f32 "
                 "{%0,%1,%2,%3}, {%4,%5,%6,%7}, {%8,%9}, {%0,%1,%2,%3};"
                 : "+f"(c[0]), "+f"(c[1]), "+f"(c[2]), "+f"(c[3])
                 : "r"(a[0]), "r"(a[1]), "r"(a[2]), "r"(a[3]), "r"(b[0]), "r"(b[1]));
}

__device__ __forceinline__ uint32_t off_km64(int row, int kk) {
    return (uint32_t)(row * 128 + ((kk ^ (row & 7)) << 4));
}
__device__ __forceinline__ uint32_t off_tr64(int k, int mc) {
    return (uint32_t)(k * 256 + ((mc ^ (k & 7)) << 4));
}
__device__ __forceinline__ uint32_t bpack(float x, float y) {
    uint32_t lo = (uint32_t)__bfloat16_as_ushort(__float2bfloat16(x));
    uint32_t hi = (uint32_t)__bfloat16_as_ushort(__float2bfloat16(y));
    return lo | (hi << 16);
}
__device__ __forceinline__ unsigned ldacq(const unsigned* p) {
    unsigned v;
    asm volatile("ld.acquire.gpu.global.u32 %0, [%1];" : "=r"(v) : "l"(p) : "memory");
    return v;
}

// ---------------- prep mega-kernel ---------------------------------------------------
__global__ __launch_bounds__(256)
void k_prep(const float* __restrict__ features, const float* __restrict__ w_cond,
            const float* __restrict__ w_out, const float* __restrict__ w_end,
            const float* __restrict__ w_skip, const float* __restrict__ w_res,
            const float* __restrict__ w_dil)
{
    __shared__ float tile[32 * 33 * 2];
    float2* tile2 = reinterpret_cast<float2*>(tile);
    const int b = blockIdx.x, tid = threadIdx.x;
    const int x = tid & 31, y = tid >> 5;

    __nv_bfloat16* WC_HI = (__nv_bfloat16*)(g_scratch + OFF_WC_HI);
    __nv_bfloat16* WC_LO = (__nv_bfloat16*)(g_scratch + OFF_WC_LO);
    __nv_bfloat16* FT_HI = (__nv_bfloat16*)(g_scratch + OFF_FT_HI);
    __nv_bfloat16* FT_LO = (__nv_bfloat16*)(g_scratch + OFF_FT_LO);

    auto tr = [&](const float* ip, float* op, int R, int C, int c0, int r0) {
#pragma unroll
        for (int i = 0; i < 32; i += 8)
            tile[(y + i) * 33 + x] = ip[(size_t)(r0 + y + i) * C + c0 + x];
        __syncthreads();
#pragma unroll
        for (int i = 0; i < 32; i += 8)
            op[(size_t)(c0 + y + i) * R + r0 + x] = tile[x * 33 + y + i];
    };

    if (b < 4096) {
        int i = b * 256 + tid;
        float4 v = reinterpret_cast<const float4*>(w_cond)[i];
        __nv_bfloat16 h0 = __float2bfloat16(v.x), h1 = __float2bfloat16(v.y);
        __nv_bfloat16 h2 = __float2bfloat16(v.z), h3 = __float2bfloat16(v.w);
        uint2 vh = make_uint2(
            (uint32_t)__bfloat16_as_ushort(h0) | ((uint32_t)__bfloat16_as_ushort(h1) << 16),
            (uint32_t)__bfloat16_as_ushort(h2) | ((uint32_t)__bfloat16_as_ushort(h3) << 16));
        uint2 vl = make_uint2(bpack(v.x - __bfloat162float(h0), v.y - __bfloat162float(h1)),
                              bpack(v.z - __bfloat162float(h2), v.w - __bfloat162float(h3)));
        reinterpret_cast<uint2*>(WC_HI)[i] = vh;
        reinterpret_cast<uint2*>(WC_LO)[i] = vl;
    } else if (b < 4352) {
        int t = b - 4096;
        int c0 = (t & 3) * 32, r0 = (t >> 2) * 32;
#pragma unroll
        for (int i = 0; i < 32; i += 8)
            tile[(y + i) * 33 + x] = features[(size_t)(r0 + y + i) * 128 + c0 + x];
        __syncthreads();
#pragma unroll
        for (int i = 0; i < 32; i += 8) {
            float v = tile[x * 33 + y + i];
            size_t o = (size_t)(c0 + y + i) * 2048 + r0 + x;
            __nv_bfloat16 h = __float2bfloat16(v);
            FT_HI[o] = h;
            FT_LO[o] = __float2bfloat16(v - __bfloat162float(h));
        }
    } else if (b < 4416) {
        int t = b - 4352;
        tr(w_out, g_scratch + OFF_WOT, 256, 256, (t & 7) * 32, (t >> 3) * 32);
    } else if (b < 4480) {
        int t = b - 4416;
        tr(w_end, g_scratch + OFF_WET, 256, 256, (t & 7) * 32, (t >> 3) * 32);
    } else if (b < 4736) {
        int t = b - 4480;
        int l = t >> 4, bx = t & 1, by = (t >> 1) & 7;
        tr(w_skip + (size_t)l * 16384, g_scratch + OFF_WSKT + (size_t)l * 16384,
           256, 64, bx * 32, by * 32);
    } else if (b < 4796) {
        int t = b - 4736;
        int l = t >> 2, bx = t & 1, by = (t >> 1) & 1;
        tr(w_res + (size_t)l * 4096, g_scratch + OFF_WRST + (size_t)l * 4096,
           64, 64, bx * 32, by * 32);
    } else if (b < 4924) {
        int t = b - 4796;
        int l = t >> 3, sub = t & 7;
        int r0 = (sub >> 1) * 32;               // c dim
        int c0 = (sub & 1) * 32;                // j dim
        const float2* ip2 = reinterpret_cast<const float2*>(w_dil + (size_t)l * 16384);
        float2* op2 = reinterpret_cast<float2*>(g_scratch + OFF_WDT) + (size_t)l * 8192;
#pragma unroll
        for (int i = 0; i < 32; i += 8)
            tile2[(y + i) * 33 + x] = ip2[(size_t)(r0 + y + i) * 64 + c0 + x];
        __syncthreads();
#pragma unroll
        for (int i = 0; i < 32; i += 8)
            op2[(size_t)(c0 + y + i) * 128 + r0 + x] = tile2[x * 33 + y + i];
    } else {
        if (tid < 8)  g_cnt1[tid] = 0u;
        if (tid < 16) g_cnt2[tid] = 0u;
        if (tid == 0) g_bar = 0u;
    }
}

// ---------------- GEMM core (bf16 A + bf16 B, K64 3-stage pipeline, 512 thr) --------
__device__ __forceinline__ void gemm_core(
    char* smem, uint32_t sb, int tid,
    const __nv_bfloat16* __restrict__ Ahi, const __nv_bfloat16* __restrict__ Alo,
    const __nv_bfloat16* __restrict__ Bhi, const __nv_bfloat16* __restrict__ Blo,
    int K, int bm, int bn, int mode, const float* __restrict__ bias,
    float* __restrict__ outF,
    __nv_bfloat16* __restrict__ outHi, __nv_bfloat16* __restrict__ outLo)
{
    const int wid = tid >> 5, lane = tid & 31;
    const int wm = (wid & 3) * 32, wn = (wid >> 2) * 32;
    const uint32_t STG = 65536;

    float acc[2][4][4];
#pragma unroll
    for (int mt = 0; mt < 2; mt++)
#pragma unroll
        for (int nt = 0; nt < 4; nt++)
#pragma unroll
            for (int i = 0; i < 4; i++) acc[mt][nt][i] = 0.0f;

    const int nsteps = K >> 6;

    auto fill_ab = [&](int s, int k0) {
        uint32_t base = sb + (uint32_t)s * STG;
#pragma unroll
        for (int i = 0; i < 2; i++) {
            int idx = tid + i * 512;
            int row = idx >> 3, kk = idx & 7;
            uint32_t d = off_km64(row, kk);
            cp16(base + d,         Ahi + (size_t)(bm + row) * K + k0 + kk * 8);
            cp16(base + 16384 + d, Alo + (size_t)(bm + row) * K + k0 + kk * 8);
            cp16(base + 32768 + d, Bhi + (size_t)(bn + row) * K + k0 + kk * 8);
            cp16(base + 49152 + d, Blo + (size_t)(bn + row) * K + k0 + kk * 8);
        }
    };

    fill_ab(0, 0);  CP_COMMIT();
    fill_ab(1, 64); CP_COMMIT();

    int sc = 0;
    for (int it = 0; it < nsteps; it++) {
        int sn = sc + 1; if (sn == 3) sn = 0;
        int sf = sn + 1; if (sf == 3) sf = 0;

        if (it < nsteps - 1)
            asm volatile("cp.async.wait_group 1;" ::: "memory");
        else
            asm volatile("cp.async.wait_group 0;" ::: "memory");
        __syncthreads();

        if (it + 2 < nsteps) { fill_ab(sf, (it + 2) * 64); CP_COMMIT(); }

        uint32_t base = sb + (uint32_t)sc * STG;
#pragma unroll
        for (int s = 0; s < 4; s++) {
            const int kk0 = s * 2;
            uint32_t af[2][2][4];
#pragma unroll
            for (int mt = 0; mt < 2; mt++) {
                int r2 = wm + mt * 16 + (lane & 15);
                int k2 = kk0 + (lane >> 4);
                uint32_t ad = off_km64(r2, k2);
                ldsm4(af[mt][0], base + ad);
                ldsm4(af[mt][1], base + 16384 + ad);
            }
            uint32_t bh[4][2], bl[4][2];
#pragma unroll
            for (int p = 0; p < 2; p++) {
                int r2 = wn + p * 16 + ((lane >> 4) << 3) + (lane & 7);
                int k2 = kk0 + ((lane >> 3) & 1);
                uint32_t bd = off_km64(r2, k2);
                uint32_t r[4];
                ldsm4(r, base + 32768 + bd);
                bh[2 * p][0] = r[0]; bh[2 * p][1] = r[1];
                bh[2 * p + 1][0] = r[2]; bh[2 * p + 1][1] = r[3];
                ldsm4(r, base + 49152 + bd);
                bl[2 * p][0] = r[0]; bl[2 * p][1] = r[1];
                bl[2 * p + 1][0] = r[2]; bl[2 * p + 1][1] = r[3];
            }
#pragma unroll
            for (int mt = 0; mt < 2; mt++)
#pragma unroll
                for (int nt = 0; nt < 4; nt++) {
                    mma_bf16(acc[mt][nt], af[mt][0], bh[nt]);
                    mma_bf16(acc[mt][nt], af[mt][0], bl[nt]);
                    mma_bf16(acc[mt][nt], af[mt][1], bh[nt]);
                }
        }
        sc = sn;
    }
    __syncthreads();

    float* sd = reinterpret_cast<float*>(smem);
#pragma unroll
    for (int mt = 0; mt < 2; mt++)
#pragma unroll
        for (int nt = 0; nt < 4; nt++) {
            int r = wm + mt * 16 + (lane >> 2);
            int c = wn + nt * 8 + (lane & 3) * 2;
            sd[r * 129 + c]           = acc[mt][nt][0];
            sd[r * 129 + c + 1]       = acc[mt][nt][1];
            sd[(r + 8) * 129 + c]     = acc[mt][nt][2];
            sd[(r + 8) * 129 + c + 1] = acc[mt][nt][3];
        }
    __syncthreads();

    if (mode == 1) {
        int mg = (tid & 31) * 4;
        int nl = tid >> 5;
        for (int n0 = 0; n0 < 128; n0 += 16) {
            int n = n0 + nl;
            uint2 vh, vl;
            __nv_bfloat16* hp = (__nv_bfloat16*)&vh;
            __nv_bfloat16* lp = (__nv_bfloat16*)&vl;
#pragma unroll
            for (int j = 0; j < 4; j++) {
                float v = sd[(mg + j) * 129 + n] + bias[bm + mg + j];
                __nv_bfloat16 h = __float2bfloat16(v);
                hp[j] = h;
                lp[j] = __float2bfloat16(v - __bfloat162float(h));
            }
            *reinterpret_cast<uint2*>(outHi + (size_t)(bn + n) * 2048 + bm + mg) = vh;
            *reinterpret_cast<uint2*>(outLo + (size_t)(bn + n) * 2048 + bm + mg) = vl;
        }
    } else {
        int mo = tid >> 7, n = tid & 127;
        int gn = bn + n;
        if (gn < T_LEN) {
            for (int m0 = 0; m0 < 128; m0 += 4) {
                int m = m0 + mo;
                outF[(size_t)(bm + m) * T_LEN + gn] = sd[m * 129 + n] + bias[bm + m];
            }
        }
    }
}

// ---------------- upsample GEMM (512 thr, persistent: 2 m-tiles per block) ----------
__global__ __launch_bounds__(512)
void k_gemm_up(const float* __restrict__ Af32,
               const __nv_bfloat16* __restrict__ Bhi, const __nv_bfloat16* __restrict__ Blo,
               const float* __restrict__ bias,
               __nv_bfloat16* __restrict__ outHi, __nv_bfloat16* __restrict__ outLo)
{
    extern __shared__ char smem[];
    uint32_t sb = s2u(smem);
    const int tid = threadIdx.x;
    const int wid = tid >> 5, lane = tid & 31;
    const int Mg = 32768, K = 2048;
    const int wm = (wid & 3) * 32, wn = (wid >> 2) * 32;
    const uint32_t STG = 65536;
    const int nsteps = K >> 6;

    for (int tile = 0; tile < 2; tile++) {
        const int bm = (blockIdx.x + tile * 128) * 128;

        float acc[2][4][4];
#pragma unroll
        for (int mt = 0; mt < 2; mt++)
#pragma unroll
            for (int nt = 0; nt < 4; nt++)
#pragma unroll
                for (int i = 0; i < 4; i++) acc[mt][nt][i] = 0.0f;

        float4 pre[4];

        auto ldg_pre = [&](int k0) {
#pragma unroll
            for (int i = 0; i < 4; i++) {
                int u = tid + i * 512;
                int k = u >> 5, f4 = u & 31;
                pre[i] = *reinterpret_cast<const float4*>(
                    Af32 + (size_t)(k0 + k) * Mg + bm + f4 * 4);
            }
        };
        auto sts_pre = [&](int s) {
#pragma unroll
            for (int i = 0; i < 4; i++) {
                int u = tid + i * 512;
                int k = u >> 5, f4 = u & 31;
                float4 v = pre[i];
                __nv_bfloat16 h0 = __float2bfloat16(v.x), h1 = __float2bfloat16(v.y);
                __nv_bfloat16 h2 = __float2bfloat16(v.z), h3 = __float2bfloat16(v.w);
                uint32_t hi01 = (uint32_t)__bfloat16_as_ushort(h0) |
                                ((uint32_t)__bfloat16_as_ushort(h1) << 16);
                uint32_t hi23 = (uint32_t)__bfloat16_as_ushort(h2) |
                                ((uint32_t)__bfloat16_as_ushort(h3) << 16);
                uint32_t lo01 = bpack(v.x - __bfloat162float(h0), v.y - __bfloat162float(h1));
                uint32_t lo23 = bpack(v.z - __bfloat162float(h2), v.w - __bfloat162float(h3));
                int mc = f4 >> 1, half = f4 & 1;
                uint32_t a = (uint32_t)s * STG + off_tr64(k, mc) + half * 8;
                *reinterpret_cast<uint2*>(smem + a) = make_uint2(hi01, hi23);
                *reinterpret_cast<uint2*>(smem + 16384 + a) = make_uint2(lo01, lo23);
            }
        };
        auto fill_b = [&](int s, int k0) {
            uint32_t base = sb + (uint32_t)s * STG;
#pragma unroll
            for (int i = 0; i < 2; i++) {
                int idx = tid + i * 512;
                int row = idx >> 3, kk = idx & 7;
                uint32_t d = off_km64(row, kk);
                cp16(base + 32768 + d, Bhi + (size_t)row * K + k0 + kk * 8);
                cp16(base + 49152 + d, Blo + (size_t)row * K + k0 + kk * 8);
            }
        };

        ldg_pre(0);
        sts_pre(0);
        ldg_pre(64);
        fill_b(0, 0);  CP_COMMIT();
        fill_b(1, 64); CP_COMMIT();

        int sc = 0;
        for (int it = 0; it < nsteps; it++) {
            int sn = sc + 1; if (sn == 3) sn = 0;
            int sf = sn + 1; if (sf == 3) sf = 0;

            if (it < nsteps - 1)
                asm volatile("cp.async.wait_group 1;" ::: "memory");
            else
                asm volatile("cp.async.wait_group 0;" ::: "memory");
            __syncthreads();

            if (it + 1 < nsteps) sts_pre(sn);
            if (it + 2 < nsteps) {
                ldg_pre((it + 2) * 64);
                fill_b(sf, (it + 2) * 64);
                CP_COMMIT();
            }

            uint32_t base = sb + (uint32_t)sc * STG;
#pragma unroll
            for (int s = 0; s < 4; s++) {
                const int kk0 = s * 2;
                uint32_t af[2][2][4];
#pragma unroll
                for (int mt = 0; mt < 2; mt++) {
                    int k  = s * 16 + ((lane >> 4) << 3) + (lane & 7);
                    int mc = ((wm + mt * 16) >> 3) + ((lane >> 3) & 1);
                    uint32_t ad = off_tr64(k, mc);
                    ldsm4t(af[mt][0], base + ad);
                    ldsm4t(af[mt][1], base + 16384 + ad);
                }
                uint32_t bh[4][2], bl[4][2];
#pragma unroll
                for (int p = 0; p < 2; p++) {
                    int r2 = wn + p * 16 + ((lane >> 4) << 3) + (lane & 7);
                    int k2 = kk0 + ((lane >> 3) & 1);
                    uint32_t bd = off_km64(r2, k2);
                    uint32_t r[4];
                    ldsm4(r, base + 32768 + bd);
                    bh[2 * p][0] = r[0]; bh[2 * p][1] = r[1];
                    bh[2 * p + 1][0] = r[2]; bh[2 * p + 1][1] = r[3];
                    ldsm4(r, base + 49152 + bd);
                    bl[2 * p][0] = r[0]; bl[2 * p][1] = r[1];
                    bl[2 * p + 1][0] = r[2]; bl[2 * p + 1][1] = r[3];
                }
#pragma unroll
                for (int mt = 0; mt < 2; mt++)
#pragma unroll
                    for (int nt = 0; nt < 4; nt++) {
                        mma_bf16(acc[mt][nt], af[mt][0], bh[nt]);
                        mma_bf16(acc[mt][nt], af[mt][0], bl[nt]);
                        mma_bf16(acc[mt][nt], af[mt][1], bh[nt]);
                    }
            }
            sc = sn;
        }
        __syncthreads();

        float* sd = reinterpret_cast<float*>(smem);
#pragma unroll
        for (int mt = 0; mt < 2; mt++)
#pragma unroll
            for (int nt = 0; nt < 4; nt++) {
                int r = wm + mt * 16 + (lane >> 2);
                int c = wn + nt * 8 + (lane & 3) * 2;
                sd[r * 129 + c]           = acc[mt][nt][0];
                sd[r * 129 + c + 1]       = acc[mt][nt][1];
                sd[(r + 8) * 129 + c]     = acc[mt][nt][2];
                sd[(r + 8) * 129 + c + 1] = acc[mt][nt][3];
            }
        __syncthreads();

        int bo = bm >> 4;
        for (int u = tid; u < T_LEN; u += 512) {
            int m = u >> 3, p = u & 7;
            uint4 vh, vl;
            __nv_bfloat16* hp = (__nv_bfloat16*)&vh;
            __nv_bfloat16* lp = (__nv_bfloat16*)&vl;
#pragma unroll
            for (int ol = 0; ol < 8; ol++) {
                float v = sd[(ol * 16 + p + 8) * 129 + m] +
                          sd[(ol * 16 + p) * 129 + m + 1] + bias[bo + ol];
                __nv_bfloat16 h = __float2bfloat16(v);
                hp[ol] = h;
                lp[ol] = __float2bfloat16(v - __bfloat162float(h));
            }
            *reinterpret_cast<uint4*>(outHi + (size_t)u * 2048 + bo) = vh;
            *reinterpret_cast<uint4*>(outLo + (size_t)u * 2048 + bo) = vl;
        }
        __syncthreads();
    }
}

// ---------------- fused: encode/embed + cond1 + cond2 + lock-step tail ---------------
__global__ __launch_bounds__(512)
void k_fused(const float* __restrict__ b_cond,
             const float* __restrict__ audio, const float* __restrict__ embed,
             const float* __restrict__ b_dil_all, const float* __restrict__ b_res_all,
             const float* __restrict__ b_skip_all,
             float* __restrict__ out, int write_q)
{
    extern __shared__ char smem[];
    uint32_t sb = s2u(smem);
    const int tid = threadIdx.x;
    const int b = blockIdx.x;
    const int t0 = b * TB;
    float* XB = g_scratch + OFF_XB;

    // ---- phase 0: encode + embed ----
    if (b < NTAIL) {
        int j = tid >> 3, tt = tid & 7;
        int t = t0 + tt;
        float x = audio[t];
        float xc = fminf(1.0f, fmaxf(-1.0f, x));
        float s  = (xc > 0.0f) ? 1.0f : ((xc < 0.0f) ? -1.0f : 0.0f);
        float num = log1pf(__fmul_rn(255.0f, fabsf(xc)));
        float den = log1pf(255.0f);
        float m = __fdiv_rn(__fmul_rn(s, num), den);
        float v = __fadd_rn(__fmul_rn(__fmul_rn(__fadd_rn(m, 1.0f), 0.5f), 255.0f), 0.5f);
        v = fminf(255.0f, fmaxf(0.0f, v));
        int q = (int)v;
        if (write_q && tid < TB) out[(size_t)256 * T_LEN + t] = (float)q;
        XB[(size_t)j * T_LEN + t0 + tt] = embed[q * 64 + j];
        __threadfence();
        __syncthreads();
        if (tid == 0) atomicAdd(&g_bar, 1u);
    }

    __nv_bfloat16* WC_HI = (__nv_bfloat16*)(g_scratch + OFF_WC_HI);
    __nv_bfloat16* WC_LO = (__nv_bfloat16*)(g_scratch + OFF_WC_LO);
    __nv_bfloat16* BR_HI = (__nv_bfloat16*)(g_scratch + OFF_BR_HI);
    __nv_bfloat16* BR_LO = (__nv_bfloat16*)(g_scratch + OFF_BR_LO);
    __nv_bfloat16* B2_HI = (__nv_bfloat16*)(g_scratch + OFF_B2_HI);
    __nv_bfloat16* B2_LO = (__nv_bfloat16*)(g_scratch + OFF_B2_LO);

    const int bm = (b >> 3) * 128, bn = (b & 7) * 128;

    // ---- phase 1: cond GEMM #1 tile ----
    gemm_core(smem, sb, tid, WC_HI, WC_LO, BR_HI, BR_LO, 2048, bm, bn, 1,
              b_cond, nullptr, B2_HI, B2_LO);
    __syncthreads();
    __threadfence();
    if (tid == 0) {
        atomicAdd(&g_cnt1[b & 7], 1u);
        while (ldacq(&g_cnt1[b & 7]) < 16u) {}
    }
    __syncthreads();

    // ---- phase 2: cond GEMM #2 tile ----
    gemm_core(smem, sb, tid, WC_HI, WC_LO, B2_HI, B2_LO, 2048, bm, bn, 2,
              b_cond, g_scratch + OFF_CACTS, nullptr, nullptr);
    __syncthreads();
    __threadfence();
    if (tid == 0) atomicAdd(&g_cnt2[b >> 3], 1u);

    if (b >= NTAIL) return;

    // ---- phase 3: lock-step tail ----
    // floats: WD2 [0,16384) | WSK [16384,32768) | WRS [32768,36864)
    //         XS0 36864 | XS1 37376 | IA 37888 (1024) | ACT 38912
    //         HS 39424 | HS2 41472  (end 43520 floats = 174080 B)
    float*  smf = reinterpret_cast<float*>(smem);
    float2* WD2 = reinterpret_cast<float2*>(smf);
    float*  WSK = smf + 16384;
    float*  WRS = smf + 32768;
    float*  XS0 = smf + 36864;
    float*  XS1 = XS0 + 512;
    float*  IA  = XS1 + 512;        // 1024 floats (all 128 channels x 8 t)
    float*  ACT = IA + 1024;
    float*  HS  = ACT + 512;
    float*  HS2 = HS + 2048;

    __syncthreads();   // smem repurpose safety

    float s_acc[4];
#pragma unroll
    for (int i = 0; i < 4; i++) s_acc[i] = 0.0f;

    const int c   = tid & 127;
    const int th  = tid >> 7;       // 0..3, 2 timesteps each
    const int row = tid & 255;
    const int part = tid >> 8;      // 0..1, 4 timesteps each

    for (int layer = 0; layer < 16; layer++) {
        const int d = 1 << (layer & 7);
        const float* xin  = XB + (size_t)(layer & 1) * XSZ;
        float*       xout = XB + (size_t)((layer + 1) & 1) * XSZ;
        const float* cond = g_scratch + OFF_CACTS + (size_t)layer * 128 * T_LEN;
        const char*  wdl  = (const char*)(g_scratch + OFF_WDT + (size_t)layer * 16384);
        const char*  wskl = (const char*)(g_scratch + OFF_WSKT + (size_t)layer * 16384);
        const char*  wrsl = (const char*)(g_scratch + OFF_WRST + (size_t)layer * 4096);

        __syncthreads();   // all prior-layer WSK/WRS reads complete before restage

        // stage all layer weights via cp.async (overlaps barrier wait)
#pragma unroll
        for (int i = 0; i < 8; i++) {
            int ch = tid + i * 512;
            cp16(sb + ch * 16, wdl + ch * 16);
            cp16(sb + 65536 + ch * 16, wskl + ch * 16);
        }
#pragma unroll
        for (int i = 0; i < 2; i++) {
            int ch = tid + i * 512;
            cp16(sb + 131072 + ch * 16, wrsl + ch * 16);
        }
        CP_COMMIT();

        // hoisted XS1 stage: own-tile x, written by own block last layer
        {
            int j = tid >> 3, tt = tid & 7;
            XS1[tid] = __ldcg(&xin[(size_t)j * T_LEN + t0 + tt]);
        }

        if (tid == 0) {
            unsigned tgt = (unsigned)NTAIL * (unsigned)(layer + 1);
            while (ldacq(&g_bar) < tgt) {}
            while (ldacq(&g_cnt2[layer]) < 8u) {}
        }
        __syncthreads();

        // XS0 stage (needs neighbors -> after barrier)
        {
            int j = tid >> 3, tt = tid & 7;
            int ta = t0 - d + tt;
            XS0[tid] = (ta >= 0) ? __ldcg(&xin[(size_t)j * T_LEN + ta]) : 0.0f;
        }
        float bd  = b_dil_all[layer * 128 + c];
        float cv0 = cond[(size_t)c * T_LEN + t0 + th * 2];
        float cv1 = cond[(size_t)c * T_LEN + t0 + th * 2 + 1];
        asm volatile("cp.async.wait_group 0;" ::: "memory");
        __syncthreads();

        // dilated conv: 2 timesteps per thread
        float a0 = 0.0f, a1 = 0.0f;
#pragma unroll 16
        for (int j = 0; j < 64; j++) {
            float2 w  = WD2[j * 128 + c];
            float2 x0 = *reinterpret_cast<const float2*>(&XS0[j * TB + th * 2]);
            float2 x1 = *reinterpret_cast<const float2*>(&XS1[j * TB + th * 2]);
            a0 += w.x * x0.x + w.y * x1.x;
            a1 += w.x * x0.y + w.y * x1.y;
        }
        a0 += bd + cv0;
        a1 += bd + cv1;

        // single-sync gate exchange: all channels publish, low half combines
        IA[c * TB + th * 2]     = a0;
        IA[c * TB + th * 2 + 1] = a1;
        __syncthreads();
        if (c < 64) {
            float g0 = IA[(c + 64) * TB + th * 2];
            float g1 = IA[(c + 64) * TB + th * 2 + 1];
            ACT[c * TB + th * 2]     = tanhf(a0) * (1.0f / (1.0f + expf(-g0)));
            ACT[c * TB + th * 2 + 1] = tanhf(a1) * (1.0f / (1.0f + expf(-g1)));
        }
        __syncthreads();

        // residual (1 timestep per thread), then arrive
        if (layer < 15) {
            int c2 = tid & 63, qq = tid >> 6;
            float r = 0.0f;
#pragma unroll 8
            for (int k = 0; k < 64; k++)
                r += WRS[k * 64 + c2] * ACT[k * TB + qq];
            float br = b_res_all[layer * 64 + c2];
            int t = t0 + qq;
            xout[(size_t)c2 * T_LEN + t] = __ldcg(&xin[(size_t)c2 * T_LEN + t]) + r + br;
            __threadfence();
            __syncthreads();
            if (tid == 0) atomicAdd(&g_bar, 1u);
        }

        // skip accumulation (4 timesteps per thread) from smem weights
        {
#pragma unroll 8
            for (int k = 0; k < 64; k++) {
                float w = WSK[k * 256 + row];
                float4 a = *reinterpret_cast<const float4*>(&ACT[k * TB + part * 4]);
                s_acc[0] += w * a.x; s_acc[1] += w * a.y;
                s_acc[2] += w * a.z; s_acc[3] += w * a.w;
            }
            float bs = b_skip_all[layer * 256 + row];
#pragma unroll
            for (int i = 0; i < 4; i++) s_acc[i] += bs;
        }
    }

    // ---- heads ----
    {
        __syncthreads();
#pragma unroll
        for (int i = 0; i < 4; i++)
            HS[row * TB + part * 4 + i] = fmaxf(s_acc[i], 0.0f);
        __syncthreads();

        const float* wo = g_scratch + OFF_WOT;
        float h[4] = {0.0f, 0.0f, 0.0f, 0.0f};
        for (int cc = 0; cc < 256; cc++) {
            float w = wo[cc * 256 + row];
            float4 v = *reinterpret_cast<const float4*>(&HS[cc * TB + part * 4]);
            h[0] += w * v.x; h[1] += w * v.y; h[2] += w * v.z; h[3] += w * v.w;
        }
#pragma unroll
        for (int i = 0; i < 4; i++)
            HS2[row * TB + part * 4 + i] = fmaxf(h[i], 0.0f);
        __syncthreads();

        const float* we = g_scratch + OFF_WET;
        float h2[4] = {0.0f, 0.0f, 0.0f, 0.0f};
        for (int cc = 0; cc < 256; cc++) {
            float w = we[cc * 256 + row];
            float4 v = *reinterpret_cast<const float4*>(&HS2[cc * TB + part * 4]);
            h2[0] += w * v.x; h2[1] += w * v.y; h2[2] += w * v.z; h2[3] += w * v.w;
        }

        if (b == 0 && part == 0) out[(size_t)row * T_LEN] = 0.0f;
#pragma unroll
        for (int i = 0; i < 4; i++) {
            int t = t0 + part * 4 + i;
            if (t + 1 < T_LEN) out[(size_t)row * T_LEN + t + 1] = h2[i];
        }
    }
}

// ---------------- launch -------------------------------------------------------------
extern "C" void kernel_launch(void* const* d_in, const int* in_sizes, int n_in,
                              void* d_out, int out_size)
{
    const float* features = (const float*)d_in[0];
    const float* audio    = (const float*)d_in[1];
    const float* w_up     = (const float*)d_in[2];
    const float* b_up     = (const float*)d_in[3];
    const float* w_cond   = (const float*)d_in[4];
    const float* b_cond   = (const float*)d_in[5];
    const float* embed    = (const float*)d_in[6];
    const float* w_dil    = (const float*)d_in[7];
    const float* b_dil    = (const float*)d_in[8];
    const float* w_res    = (const float*)d_in[9];
    const float* b_res    = (const float*)d_in[10];
    const float* w_skip   = (const float*)d_in[11];
    const float* b_skip   = (const float*)d_in[12];
    const float* w_out    = (const float*)d_in[13];
    const float* w_end    = (const float*)d_in[14];
    float* out = (float*)d_out;

    float* scr = nullptr;
    cudaGetSymbolAddress((void**)&scr, g_scratch);

    __nv_bfloat16* FT_HI = (__nv_bfloat16*)(scr + OFF_FT_HI);
    __nv_bfloat16* FT_LO = (__nv_bfloat16*)(scr + OFF_FT_LO);
    __nv_bfloat16* BR_HI = (__nv_bfloat16*)(scr + OFF_BR_HI);
    __nv_bfloat16* BR_LO = (__nv_bfloat16*)(scr + OFF_BR_LO);

    cudaFuncSetAttribute(k_gemm_up, cudaFuncAttributeMaxDynamicSharedMemorySize, 196608);
    cudaFuncSetAttribute(k_fused,   cudaFuncAttributeMaxDynamicSharedMemorySize, 196608);

    int write_q = (out_size >= 256 * T_LEN + T_LEN) ? 1 : 0;

    // [1] prep
    k_prep<<<4925, 256>>>(features, w_cond, w_out, w_end, w_skip, w_res, w_dil);
    // [2] upsample GEMM (512 thr, persistent, 2 tiles/block)
    k_gemm_up<<<128, 512, 196608>>>(w_up, FT_HI, FT_LO, b_up, BR_HI, BR_LO);
    // [3] fused encode/embed + cond1 + cond2 + tail
    k_fused<<<128, 512, 196608>>>(b_cond, audio, embed, b_dil, b_res, b_skip,
                                  out, write_q);
}

// round 16
// speedup vs baseline: 1.1838x; 1.1778x over previous
#include <cuda_runtime.h>
#include <cuda_fp16.h>
#include <math.h>
#include <stdint.h>

#define T_LEN 1016
#define TB 8
#define NTAIL 127
#define XSZ 65024

// ---------------- scratch layout (float units) -------------------------------------
constexpr size_t OFF_WC_HI  = 0;                                  // f16[2048*2048]
constexpr size_t OFF_WC_LO  = OFF_WC_HI  + 2097152;
constexpr size_t OFF_FT     = OFF_WC_LO  + 2097152;               // f16[128*2048]
constexpr size_t OFF_BR     = OFF_FT     + 131072;                // f16[1024*2048]
constexpr size_t OFF_B2     = OFF_BR     + 1048576;               // f16[1024*2048]
constexpr size_t OFF_CACTS  = OFF_B2     + 1048576;
constexpr size_t OFF_WOT    = OFF_CACTS  + 2080768;
constexpr size_t OFF_WET    = OFF_WOT    + 65536;
constexpr size_t OFF_XB     = OFF_WET    + 65536;                 // 2 x buffers
constexpr size_t OFF_WSKT   = OFF_XB     + 2 * (size_t)XSZ;
constexpr size_t OFF_WRST   = OFF_WSKT   + 262144;
constexpr size_t OFF_WDT    = OFF_WRST   + 61440;                 // [l][j][c] float2
constexpr size_t SCRATCH_SZ = OFF_WDT + 262144;

__device__ __align__(1024) float g_scratch[SCRATCH_SZ];
__device__ unsigned g_bar;
__device__ unsigned g_cnt1[8];
__device__ unsigned g_cnt2[16];

// ---------------- PTX helpers -------------------------------------------------------
__device__ __forceinline__ uint32_t s2u(const void* p) {
    uint32_t a;
    asm("{ .reg .u64 t; cvta.to.shared.u64 t, %1; cvt.u32.u64 %0, t; }" : "=r"(a) : "l"(p));
    return a;
}
__device__ __forceinline__ void cp16(uint32_t dst, const void* src) {
    asm volatile("cp.async.cg.shared.global [%0], [%1], 16;" :: "r"(dst), "l"(src));
}
#define CP_COMMIT() asm volatile("cp.async.commit_group;" ::: "memory")

__device__ __forceinline__ void ldsm4(uint32_t* r, uint32_t a) {
    asm volatile("ldmatrix.sync.aligned.m8n8.x4.shared.b16 {%0,%1,%2,%3}, [%4];"
                 : "=r"(r[0]), "=r"(r[1]), "=r"(r[2]), "=r"(r[3]) : "r"(a));
}
__device__ __forceinline__ void ldsm4t(uint32_t* r, uint32_t a) {
    asm volatile("ldmatrix.sync.aligned.m8n8.x4.trans.shared.b16 {%0,%1,%2,%3}, [%4];"
                 : "=r"(r[0]), "=r"(r[1]), "=r"(r[2]), "=r"(r[3]) : "r"(a));
}
__device__ __forceinline__ void mma_f16(float* c, const uint32_t* a, const uint32_t* b) {
    asm volatile("mma.sync.aligned.m16n8k16.row.col.f32.f16.f16.f32 "
                 "{%0,%1,%2,%3}, {%4,%5,%6,%7}, {%8,%9}, {%0,%1,%2,%3};"
                 : "+f"(c[0]), "+f"(c[1]), "+f"(c[2]), "+f"(c[3])
                 : "r"(a[0]), "r"(a[1]), "r"(a[2]), "r"(a[3]), "r"(b[0]), "r"(b[1]));
}

__device__ __forceinline__ uint32_t off_km64(int row, int kk) {
    return (uint32_t)(row * 128 + ((kk ^ (row & 7)) << 4));
}
__device__ __forceinline__ uint32_t off_tr64(int k, int mc) {
    return (uint32_t)(k * 256 + ((mc ^ (k & 7)) << 4));
}
__device__ __forceinline__ uint32_t hpack(float x, float y) {
    uint32_t lo = (uint32_t)__half_as_ushort(__float2half_rn(x));
    uint32_t hi = (uint32_t)__half_as_ushort(__float2half_rn(y));
    return lo | (hi << 16);
}
__device__ __forceinline__ unsigned ldacq(const unsigned* p) {
    unsigned v;
    asm volatile("ld.acquire.gpu.global.u32 %0, [%1];" : "=r"(v) : "l"(p) : "memory");
    return v;
}

// ---------------- prep mega-kernel ---------------------------------------------------
__global__ __launch_bounds__(256)
void k_prep(const float* __restrict__ features, const float* __restrict__ w_cond,
            const float* __restrict__ w_out, const float* __restrict__ w_end,
            const float* __restrict__ w_skip, const float* __restrict__ w_res,
            const float* __restrict__ w_dil)
{
    __shared__ float tile[32 * 33 * 2];
    float2* tile2 = reinterpret_cast<float2*>(tile);
    const int b = blockIdx.x, tid = threadIdx.x;
    const int x = tid & 31, y = tid >> 5;

    __half* WC_HI = (__half*)(g_scratch + OFF_WC_HI);
    __half* WC_LO = (__half*)(g_scratch + OFF_WC_LO);
    __half* FT    = (__half*)(g_scratch + OFF_FT);

    auto tr = [&](const float* ip, float* op, int R, int C, int c0, int r0) {
#pragma unroll
        for (int i = 0; i < 32; i += 8)
            tile[(y + i) * 33 + x] = ip[(size_t)(r0 + y + i) * C + c0 + x];
        __syncthreads();
#pragma unroll
        for (int i = 0; i < 32; i += 8)
            op[(size_t)(c0 + y + i) * R + r0 + x] = tile[x * 33 + y + i];
    };

    if (b < 4096) {
        int i = b * 256 + tid;
        float4 v = reinterpret_cast<const float4*>(w_cond)[i];
        __half h0 = __float2half_rn(v.x), h1 = __float2half_rn(v.y);
        __half h2 = __float2half_rn(v.z), h3 = __float2half_rn(v.w);
        uint2 vh = make_uint2(
            (uint32_t)__half_as_ushort(h0) | ((uint32_t)__half_as_ushort(h1) << 16),
            (uint32_t)__half_as_ushort(h2) | ((uint32_t)__half_as_ushort(h3) << 16));
        uint2 vl = make_uint2(hpack(v.x - __half2float(h0), v.y - __half2float(h1)),
                              hpack(v.z - __half2float(h2), v.w - __half2float(h3)));
        reinterpret_cast<uint2*>(WC_HI)[i] = vh;
        reinterpret_cast<uint2*>(WC_LO)[i] = vl;
    } else if (b < 4352) {
        int t = b - 4096;
        int c0 = (t & 3) * 32, r0 = (t >> 2) * 32;
#pragma unroll
        for (int i = 0; i < 32; i += 8)
            tile[(y + i) * 33 + x] = features[(size_t)(r0 + y + i) * 128 + c0 + x];
        __syncthreads();
#pragma unroll
        for (int i = 0; i < 32; i += 8) {
            float v = tile[x * 33 + y + i];
            size_t o = (size_t)(c0 + y + i) * 2048 + r0 + x;
            FT[o] = __float2half_rn(v);
        }
    } else if (b < 4416) {
        int t = b - 4352;
        tr(w_out, g_scratch + OFF_WOT, 256, 256, (t & 7) * 32, (t >> 3) * 32);
    } else if (b < 4480) {
        int t = b - 4416;
        tr(w_end, g_scratch + OFF_WET, 256, 256, (t & 7) * 32, (t >> 3) * 32);
    } else if (b < 4736) {
        int t = b - 4480;
        int l = t >> 4, bx = t & 1, by = (t >> 1) & 7;
        tr(w_skip + (size_t)l * 16384, g_scratch + OFF_WSKT + (size_t)l * 16384,
           256, 64, bx * 32, by * 32);
    } else if (b < 4796) {
        int t = b - 4736;
        int l = t >> 2, bx = t & 1, by = (t >> 1) & 1;
        tr(w_res + (size_t)l * 4096, g_scratch + OFF_WRST + (size_t)l * 4096,
           64, 64, bx * 32, by * 32);
    } else if (b < 4924) {
        int t = b - 4796;
        int l = t >> 3, sub = t & 7;
        int r0 = (sub >> 1) * 32;               // c dim
        int c0 = (sub & 1) * 32;                // j dim
        const float2* ip2 = reinterpret_cast<const float2*>(w_dil + (size_t)l * 16384);
        float2* op2 = reinterpret_cast<float2*>(g_scratch + OFF_WDT) + (size_t)l * 8192;
#pragma unroll
        for (int i = 0; i < 32; i += 8)
            tile2[(y + i) * 33 + x] = ip2[(size_t)(r0 + y + i) * 64 + c0 + x];
        __syncthreads();
#pragma unroll
        for (int i = 0; i < 32; i += 8)
            op2[(size_t)(c0 + y + i) * 128 + r0 + x] = tile2[x * 33 + y + i];
    } else {
        if (tid < 8)  g_cnt1[tid] = 0u;
        if (tid < 16) g_cnt2[tid] = 0u;
        if (tid == 0) g_bar = 0u;
    }
}

// ---------------- GEMM core (fp16: A hi/lo split, B single; 2-term) -----------------
__device__ __forceinline__ void gemm_core(
    char* smem, uint32_t sb, int tid,
    const __half* __restrict__ Ahi, const __half* __restrict__ Alo,
    const __half* __restrict__ B,
    int K, int bm, int bn, int mode, const float* __restrict__ bias,
    float* __restrict__ outF, __half* __restrict__ outH)
{
    const int wid = tid >> 5, lane = tid & 31;
    const int wm = (wid & 3) * 32, wn = (wid >> 2) * 32;
    const uint32_t STG = 65536;

    float acc[2][4][4];
#pragma unroll
    for (int mt = 0; mt < 2; mt++)
#pragma unroll
        for (int nt = 0; nt < 4; nt++)
#pragma unroll
            for (int i = 0; i < 4; i++) acc[mt][nt][i] = 0.0f;

    const int nsteps = K >> 6;

    auto fill_ab = [&](int s, int k0) {
        uint32_t base = sb + (uint32_t)s * STG;
#pragma unroll
        for (int i = 0; i < 2; i++) {
            int idx = tid + i * 512;
            int row = idx >> 3, kk = idx & 7;
            uint32_t d = off_km64(row, kk);
            cp16(base + d,         Ahi + (size_t)(bm + row) * K + k0 + kk * 8);
            cp16(base + 16384 + d, Alo + (size_t)(bm + row) * K + k0 + kk * 8);
            cp16(base + 32768 + d, B   + (size_t)(bn + row) * K + k0 + kk * 8);
        }
    };

    fill_ab(0, 0);  CP_COMMIT();
    fill_ab(1, 64); CP_COMMIT();

    int sc = 0;
    for (int it = 0; it < nsteps; it++) {
        int sn = sc + 1; if (sn == 3) sn = 0;
        int sf = sn + 1; if (sf == 3) sf = 0;

        if (it < nsteps - 1)
            asm volatile("cp.async.wait_group 1;" ::: "memory");
        else
            asm volatile("cp.async.wait_group 0;" ::: "memory");
        __syncthreads();

        if (it + 2 < nsteps) { fill_ab(sf, (it + 2) * 64); CP_COMMIT(); }

        uint32_t base = sb + (uint32_t)sc * STG;
#pragma unroll
        for (int s = 0; s < 4; s++) {
            const int kk0 = s * 2;
            uint32_t af[2][2][4];
#pragma unroll
            for (int mt = 0; mt < 2; mt++) {
                int r2 = wm + mt * 16 + (lane & 15);
                int k2 = kk0 + (lane >> 4);
                uint32_t ad = off_km64(r2, k2);
                ldsm4(af[mt][0], base + ad);
                ldsm4(af[mt][1], base + 16384 + ad);
            }
            uint32_t bh[4][2];
#pragma unroll
            for (int p = 0; p < 2; p++) {
                int r2 = wn + p * 16 + ((lane >> 4) << 3) + (lane & 7);
                int k2 = kk0 + ((lane >> 3) & 1);
                uint32_t bd = off_km64(r2, k2);
                uint32_t r[4];
                ldsm4(r, base + 32768 + bd);
                bh[2 * p][0] = r[0]; bh[2 * p][1] = r[1];
                bh[2 * p + 1][0] = r[2]; bh[2 * p + 1][1] = r[3];
            }
#pragma unroll
            for (int mt = 0; mt < 2; mt++)
#pragma unroll
                for (int nt = 0; nt < 4; nt++) {
                    mma_f16(acc[mt][nt], af[mt][0], bh[nt]);
                    mma_f16(acc[mt][nt], af[mt][1], bh[nt]);
                }
        }
        sc = sn;
    }
    __syncthreads();

    float* sd = reinterpret_cast<float*>(smem);
#pragma unroll
    for (int mt = 0; mt < 2; mt++)
#pragma unroll
        for (int nt = 0; nt < 4; nt++) {
            int r = wm + mt * 16 + (lane >> 2);
            int c = wn + nt * 8 + (lane & 3) * 2;
            sd[r * 129 + c]           = acc[mt][nt][0];
            sd[r * 129 + c + 1]       = acc[mt][nt][1];
            sd[(r + 8) * 129 + c]     = acc[mt][nt][2];
            sd[(r + 8) * 129 + c + 1] = acc[mt][nt][3];
        }
    __syncthreads();

    if (mode == 1) {
        int mg = (tid & 31) * 4;
        int nl = tid >> 5;
        for (int n0 = 0; n0 < 128; n0 += 16) {
            int n = n0 + nl;
            uint2 vh;
            __half* hp = (__half*)&vh;
#pragma unroll
            for (int j = 0; j < 4; j++) {
                float v = sd[(mg + j) * 129 + n] + bias[bm + mg + j];
                hp[j] = __float2half_rn(v);
            }
            *reinterpret_cast<uint2*>(outH + (size_t)(bn + n) * 2048 + bm + mg) = vh;
        }
    } else {
        int mo = tid >> 7, n = tid & 127;
        int gn = bn + n;
        if (gn < T_LEN) {
            for (int m0 = 0; m0 < 128; m0 += 4) {
                int m = m0 + mo;
                outF[(size_t)(bm + m) * T_LEN + gn] = sd[m * 129 + n] + bias[bm + m];
            }
        }
    }
}

// ---------------- upsample GEMM (fp16 2-term, 512 thr, 2 m-tiles per block) ---------
__global__ __launch_bounds__(512)
void k_gemm_up(const float* __restrict__ Af32,
               const __half* __restrict__ B,
               const float* __restrict__ bias,
               __half* __restrict__ outH)
{
    extern __shared__ char smem[];
    uint32_t sb = s2u(smem);
    const int tid = threadIdx.x;
    const int wid = tid >> 5, lane = tid & 31;
    const int Mg = 32768, K = 2048;
    const int wm = (wid & 3) * 32, wn = (wid >> 2) * 32;
    const uint32_t STG = 65536;
    const int nsteps = K >> 6;

    for (int tile = 0; tile < 2; tile++) {
        const int bm = (blockIdx.x + tile * 128) * 128;

        float acc[2][4][4];
#pragma unroll
        for (int mt = 0; mt < 2; mt++)
#pragma unroll
            for (int nt = 0; nt < 4; nt++)
#pragma unroll
                for (int i = 0; i < 4; i++) acc[mt][nt][i] = 0.0f;

        float4 pre[4];

        auto ldg_pre = [&](int k0) {
#pragma unroll
            for (int i = 0; i < 4; i++) {
                int u = tid + i * 512;
                int k = u >> 5, f4 = u & 31;
                pre[i] = *reinterpret_cast<const float4*>(
                    Af32 + (size_t)(k0 + k) * Mg + bm + f4 * 4);
            }
        };
        auto sts_pre = [&](int s) {
#pragma unroll
            for (int i = 0; i < 4; i++) {
                int u = tid + i * 512;
                int k = u >> 5, f4 = u & 31;
                float4 v = pre[i];
                __half h0 = __float2half_rn(v.x), h1 = __float2half_rn(v.y);
                __half h2 = __float2half_rn(v.z), h3 = __float2half_rn(v.w);
                uint32_t hi01 = (uint32_t)__half_as_ushort(h0) |
                                ((uint32_t)__half_as_ushort(h1) << 16);
                uint32_t hi23 = (uint32_t)__half_as_ushort(h2) |
                                ((uint32_t)__half_as_ushort(h3) << 16);
                uint32_t lo01 = hpack(v.x - __half2float(h0), v.y - __half2float(h1));
                uint32_t lo23 = hpack(v.z - __half2float(h2), v.w - __half2float(h3));
                int mc = f4 >> 1, half = f4 & 1;
                uint32_t a = (uint32_t)s * STG + off_tr64(k, mc) + half * 8;
                *reinterpret_cast<uint2*>(smem + a) = make_uint2(hi01, hi23);
                *reinterpret_cast<uint2*>(smem + 16384 + a) = make_uint2(lo01, lo23);
            }
        };
        auto fill_b = [&](int s, int k0) {
            uint32_t base = sb + (uint32_t)s * STG;
#pragma unroll
            for (int i = 0; i < 2; i++) {
                int idx = tid + i * 512;
                int row = idx >> 3, kk = idx & 7;
                uint32_t d = off_km64(row, kk);
                cp16(base + 32768 + d, B + (size_t)row * K + k0 + kk * 8);
            }
        };

        ldg_pre(0);
        sts_pre(0);
        ldg_pre(64);
        fill_b(0, 0);  CP_COMMIT();
        fill_b(1, 64); CP_COMMIT();

        int sc = 0;
        for (int it = 0; it < nsteps; it++) {
            int sn = sc + 1; if (sn == 3) sn = 0;
            int sf = sn + 1; if (sf == 3) sf = 0;

            if (it < nsteps - 1)
                asm volatile("cp.async.wait_group 1;" ::: "memory");
            else
                asm volatile("cp.async.wait_group 0;" ::: "memory");
            __syncthreads();

            if (it + 1 < nsteps) sts_pre(sn);
            if (it + 2 < nsteps) {
                ldg_pre((it + 2) * 64);
                fill_b(sf, (it + 2) * 64);
                CP_COMMIT();
            }

            uint32_t base = sb + (uint32_t)sc * STG;
#pragma unroll
            for (int s = 0; s < 4; s++) {
                const int kk0 = s * 2;
                uint32_t af[2][2][4];
#pragma unroll
                for (int mt = 0; mt < 2; mt++) {
                    int k  = s * 16 + ((lane >> 4) << 3) + (lane & 7);
                    int mc = ((wm + mt * 16) >> 3) + ((lane >> 3) & 1);
                    uint32_t ad = off_tr64(k, mc);
                    ldsm4t(af[mt][0], base + ad);
                    ldsm4t(af[mt][1], base + 16384 + ad);
                }
                uint32_t bh[4][2];
#pragma unroll
                for (int p = 0; p < 2; p++) {
                    int r2 = wn + p * 16 + ((lane >> 4) << 3) + (lane & 7);
                    int k2 = kk0 + ((lane >> 3) & 1);
                    uint32_t bd = off_km64(r2, k2);
                    uint32_t r[4];
                    ldsm4(r, base + 32768 + bd);
                    bh[2 * p][0] = r[0]; bh[2 * p][1] = r[1];
                    bh[2 * p + 1][0] = r[2]; bh[2 * p + 1][1] = r[3];
                }
#pragma unroll
                for (int mt = 0; mt < 2; mt++)
#pragma unroll
                    for (int nt = 0; nt < 4; nt++) {
                        mma_f16(acc[mt][nt], af[mt][0], bh[nt]);
                        mma_f16(acc[mt][nt], af[mt][1], bh[nt]);
                    }
            }
            sc = sn;
        }
        __syncthreads();

        float* sd = reinterpret_cast<float*>(smem);
#pragma unroll
        for (int mt = 0; mt < 2; mt++)
#pragma unroll
            for (int nt = 0; nt < 4; nt++) {
                int r = wm + mt * 16 + (lane >> 2);
                int c = wn + nt * 8 + (lane & 3) * 2;
                sd[r * 129 + c]           = acc[mt][nt][0];
                sd[r * 129 + c + 1]       = acc[mt][nt][1];
                sd[(r + 8) * 129 + c]     = acc[mt][nt][2];
                sd[(r + 8) * 129 + c + 1] = acc[mt][nt][3];
            }
        __syncthreads();

        int bo = bm >> 4;
        for (int u = tid; u < T_LEN; u += 512) {
            int m = u >> 3, p = u & 7;
            uint4 vh;
            __half* hp = (__half*)&vh;
#pragma unroll
            for (int ol = 0; ol < 8; ol++) {
                float v = sd[(ol * 16 + p + 8) * 129 + m] +
                          sd[(ol * 16 + p) * 129 + m + 1] + bias[bo + ol];
                hp[ol] = __float2half_rn(v);
            }
            *reinterpret_cast<uint4*>(outH + (size_t)u * 2048 + bo) = vh;
        }
        __syncthreads();
    }
}

// ---------------- fused: encode/embed + cond1 + cond2 + lock-step tail ---------------
__global__ __launch_bounds__(512)
void k_fused(const float* __restrict__ b_cond,
             const float* __restrict__ audio, const float* __restrict__ embed,
             const float* __restrict__ b_dil_all, const float* __restrict__ b_res_all,
             const float* __restrict__ b_skip_all,
             float* __restrict__ out, int write_q)
{
    extern __shared__ char smem[];
    uint32_t sb = s2u(smem);
    const int tid = threadIdx.x;
    const int b = blockIdx.x;
    const int t0 = b * TB;
    float* XB = g_scratch + OFF_XB;

    // ---- phase 0: encode + embed ----
    if (b < NTAIL) {
        int j = tid >> 3, tt = tid & 7;
        int t = t0 + tt;
        float x = audio[t];
        float xc = fminf(1.0f, fmaxf(-1.0f, x));
        float s  = (xc > 0.0f) ? 1.0f : ((xc < 0.0f) ? -1.0f : 0.0f);
        float num = log1pf(__fmul_rn(255.0f, fabsf(xc)));
        float den = log1pf(255.0f);
        float m = __fdiv_rn(__fmul_rn(s, num), den);
        float v = __fadd_rn(__fmul_rn(__fmul_rn(__fadd_rn(m, 1.0f), 0.5f), 255.0f), 0.5f);
        v = fminf(255.0f, fmaxf(0.0f, v));
        int q = (int)v;
        if (write_q && tid < TB) out[(size_t)256 * T_LEN + t] = (float)q;
        XB[(size_t)j * T_LEN + t0 + tt] = embed[q * 64 + j];
        __threadfence();
        __syncthreads();
        if (tid == 0) atomicAdd(&g_bar, 1u);
    }

    __half* WC_HI = (__half*)(g_scratch + OFF_WC_HI);
    __half* WC_LO = (__half*)(g_scratch + OFF_WC_LO);
    __half* BR    = (__half*)(g_scratch + OFF_BR);
    __half* B2    = (__half*)(g_scratch + OFF_B2);

    const int bm = (b >> 3) * 128, bn = (b & 7) * 128;

    // ---- phase 1: cond GEMM #1 tile ----
    gemm_core(smem, sb, tid, WC_HI, WC_LO, BR, 2048, bm, bn, 1,
              b_cond, nullptr, B2);
    __syncthreads();
    __threadfence();
    if (tid == 0) {
        atomicAdd(&g_cnt1[b & 7], 1u);
        while (ldacq(&g_cnt1[b & 7]) < 16u) {}
    }
    __syncthreads();

    // ---- phase 2: cond GEMM #2 tile ----
    gemm_core(smem, sb, tid, WC_HI, WC_LO, B2, 2048, bm, bn, 2,
              b_cond, g_scratch + OFF_CACTS, nullptr);
    __syncthreads();
    __threadfence();
    if (tid == 0) atomicAdd(&g_cnt2[b >> 3], 1u);

    if (b >= NTAIL) return;

    // ---- phase 3: lock-step tail ----
    float*  smf = reinterpret_cast<float*>(smem);
    float2* WD2 = reinterpret_cast<float2*>(smf);
    float*  WSK = smf + 16384;
    float*  WRS = smf + 32768;
    float*  XS0 = smf + 36864;
    float*  XS1 = XS0 + 512;
    float*  IA  = XS1 + 512;
    float*  ACT = IA + 512;
    float*  HS  = ACT + 512;
    float*  HS2 = HS + 2048;

    __syncthreads();   // smem repurpose safety

    float s_acc[4];
#pragma unroll
    for (int i = 0; i < 4; i++) s_acc[i] = 0.0f;

    const int c   = tid & 127;
    const int th  = tid >> 7;       // 0..3, 2 timesteps each
    const int row = tid & 255;
    const int part = tid >> 8;      // 0..1, 4 timesteps each

    for (int layer = 0; layer < 16; layer++) {
        const int d = 1 << (layer & 7);
        const float* xin  = XB + (size_t)(layer & 1) * XSZ;
        float*       xout = XB + (size_t)((layer + 1) & 1) * XSZ;
        const float* cond = g_scratch + OFF_CACTS + (size_t)layer * 128 * T_LEN;
        const char*  wdl  = (const char*)(g_scratch + OFF_WDT + (size_t)layer * 16384);
        const char*  wskl = (const char*)(g_scratch + OFF_WSKT + (size_t)layer * 16384);
        const char*  wrsl = (const char*)(g_scratch + OFF_WRST + (size_t)layer * 4096);

        __syncthreads();   // all prior-layer WSK/WRS reads complete before restage

        // stage all layer weights via cp.async (overlaps barrier wait)
#pragma unroll
        for (int i = 0; i < 8; i++) {
            int ch = tid + i * 512;
            cp16(sb + ch * 16, wdl + ch * 16);
            cp16(sb + 65536 + ch * 16, wskl + ch * 16);
        }
#pragma unroll
        for (int i = 0; i < 2; i++) {
            int ch = tid + i * 512;
            cp16(sb + 131072 + ch * 16, wrsl + ch * 16);
        }
        CP_COMMIT();

        if (tid == 0) {
            unsigned tgt = (unsigned)NTAIL * (unsigned)(layer + 1);
            while (ldacq(&g_bar) < tgt) {}
            while (ldacq(&g_cnt2[layer]) < 8u) {}
        }
        __syncthreads();

        // stage x windows
        {
            int j = tid >> 3, tt = tid & 7;
            int ta = t0 - d + tt;
            XS0[tid] = (ta >= 0) ? __ldcg(&xin[(size_t)j * T_LEN + ta]) : 0.0f;
            XS1[tid] = __ldcg(&xin[(size_t)j * T_LEN + t0 + tt]);
        }
        float bd  = b_dil_all[layer * 128 + c];
        float cv0 = cond[(size_t)c * T_LEN + t0 + th * 2];
        float cv1 = cond[(size_t)c * T_LEN + t0 + th * 2 + 1];
        asm volatile("cp.async.wait_group 0;" ::: "memory");
        __syncthreads();

        // dilated conv: 2 timesteps per thread
        float a0 = 0.0f, a1 = 0.0f;
#pragma unroll 16
        for (int j = 0; j < 64; j++) {
            float2 w  = WD2[j * 128 + c];
            float2 x0 = *reinterpret_cast<const float2*>(&XS0[j * TB + th * 2]);
            float2 x1 = *reinterpret_cast<const float2*>(&XS1[j * TB + th * 2]);
            a0 += w.x * x0.x + w.y * x1.x;
            a1 += w.x * x0.y + w.y * x1.y;
        }
        a0 += bd + cv0;
        a1 += bd + cv1;

        __syncthreads();
        if (c >= 64) {
            IA[(c - 64) * TB + th * 2]     = a0;
            IA[(c - 64) * TB + th * 2 + 1] = a1;
        }
        __syncthreads();
        if (c < 64) {
            float g0 = IA[c * TB + th * 2];
            float g1 = IA[c * TB + th * 2 + 1];
            ACT[c * TB + th * 2]     = tanhf(a0) * (1.0f / (1.0f + expf(-g0)));
            ACT[c * TB + th * 2 + 1] = tanhf(a1) * (1.0f / (1.0f + expf(-g1)));
        }
        __syncthreads();

        // residual (1 timestep per thread), then arrive
        if (layer < 15) {
            int c2 = tid & 63, qq = tid >> 6;
            float r = 0.0f;
#pragma unroll 8
            for (int k = 0; k < 64; k++)
                r += WRS[k * 64 + c2] * ACT[k * TB + qq];
            float br = b_res_all[layer * 64 + c2];
            int t = t0 + qq;
            xout[(size_t)c2 * T_LEN + t] = __ldcg(&xin[(size_t)c2 * T_LEN + t]) + r + br;
            __threadfence();
            __syncthreads();
            if (tid == 0) atomicAdd(&g_bar, 1u);
        }

        // skip accumulation (4 timesteps per thread) from smem weights
        {
#pragma unroll 8
            for (int k = 0; k < 64; k++) {
                float w = WSK[k * 256 + row];
                float4 a = *reinterpret_cast<const float4*>(&ACT[k * TB + part * 4]);
                s_acc[0] += w * a.x; s_acc[1] += w * a.y;
                s_acc[2] += w * a.z; s_acc[3] += w * a.w;
            }
            float bs = b_skip_all[layer * 256 + row];
#pragma unroll
            for (int i = 0; i < 4; i++) s_acc[i] += bs;
        }
    }

    // ---- heads ----
    {
        __syncthreads();
#pragma unroll
        for (int i = 0; i < 4; i++)
            HS[row * TB + part * 4 + i] = fmaxf(s_acc[i], 0.0f);
        __syncthreads();

        const float* wo = g_scratch + OFF_WOT;
        float h[4] = {0.0f, 0.0f, 0.0f, 0.0f};
        for (int cc = 0; cc < 256; cc++) {
            float w = wo[cc * 256 + row];
            float4 v = *reinterpret_cast<const float4*>(&HS[cc * TB + part * 4]);
            h[0] += w * v.x; h[1] += w * v.y; h[2] += w * v.z; h[3] += w * v.w;
        }
#pragma unroll
        for (int i = 0; i < 4; i++)
            HS2[row * TB + part * 4 + i] = fmaxf(h[i], 0.0f);
        __syncthreads();

        const float* we = g_scratch + OFF_WET;
        float h2[4] = {0.0f, 0.0f, 0.0f, 0.0f};
        for (int cc = 0; cc < 256; cc++) {
            float w = we[cc * 256 + row];
            float4 v = *reinterpret_cast<const float4*>(&HS2[cc * TB + part * 4]);
            h2[0] += w * v.x; h2[1] += w * v.y; h2[2] += w * v.z; h2[3] += w * v.w;
        }

        if (b == 0 && part == 0) out[(size_t)row * T_LEN] = 0.0f;
#pragma unroll
        for (int i = 0; i < 4; i++) {
            int t = t0 + part * 4 + i;
            if (t + 1 < T_LEN) out[(size_t)row * T_LEN + t + 1] = h2[i];
        }
    }
}

// ---------------- launch -------------------------------------------------------------
extern "C" void kernel_launch(void* const* d_in, const int* in_sizes, int n_in,
                              void* d_out, int out_size)
{
    const float* features = (const float*)d_in[0];
    const float* audio    = (const float*)d_in[1];
    const float* w_up     = (const float*)d_in[2];
    const float* b_up     = (const float*)d_in[3];
    const float* w_cond   = (const float*)d_in[4];
    const float* b_cond   = (const float*)d_in[5];
    const float* embed    = (const float*)d_in[6];
    const float* w_dil    = (const float*)d_in[7];
    const float* b_dil    = (const float*)d_in[8];
    const float* w_res    = (const float*)d_in[9];
    const float* b_res    = (const float*)d_in[10];
    const float* w_skip   = (const float*)d_in[11];
    const float* b_skip   = (const float*)d_in[12];
    const float* w_out    = (const float*)d_in[13];
    const float* w_end    = (const float*)d_in[14];
    float* out = (float*)d_out;

    float* scr = nullptr;
    cudaGetSymbolAddress((void**)&scr, g_scratch);

    __half* FT = (__half*)(scr + OFF_FT);
    __half* BR = (__half*)(scr + OFF_BR);

    cudaFuncSetAttribute(k_gemm_up, cudaFuncAttributeMaxDynamicSharedMemorySize, 196608);
    cudaFuncSetAttribute(k_fused,   cudaFuncAttributeMaxDynamicSharedMemorySize, 196608);

    int write_q = (out_size >= 256 * T_LEN + T_LEN) ? 1 : 0;

    // [1] prep
    k_prep<<<4925, 256>>>(features, w_cond, w_out, w_end, w_skip, w_res, w_dil);
    // [2] upsample GEMM (fp16 2-term, 512 thr, 2 tiles/block)
    k_gemm_up<<<128, 512, 196608>>>(w_up, FT, b_up, BR);
    // [3] fused encode/embed + cond1 + cond2 + tail
    k_fused<<<128, 512, 196608>>>(b_cond, audio, embed, b_dil, b_res, b_skip,
                                  out, write_q);
}

// round 17
// speedup vs baseline: 1.5260x; 1.2890x over previous
#include <cuda_runtime.h>
#include <cuda_fp16.h>
#include <math.h>
#include <stdint.h>

#define T_LEN 1016
#define TB 8
#define NTAIL 127
#define XSZ 65024

// ---------------- scratch layout (float units) -------------------------------------
constexpr size_t OFF_WC     = 0;                                  // f16[2048*2048]
constexpr size_t OFF_FT     = OFF_WC     + 2097152;               // f16[128*2048]
constexpr size_t OFF_BR     = OFF_FT     + 131072;                // f16[1024*2048]
constexpr size_t OFF_B2     = OFF_BR     + 1048576;               // f16[1024*2048]
constexpr size_t OFF_CACTS  = OFF_B2     + 1048576;
constexpr size_t OFF_WOT    = OFF_CACTS  + 2080768;
constexpr size_t OFF_WET    = OFF_WOT    + 65536;
constexpr size_t OFF_XB     = OFF_WET    + 65536;                 // 2 x buffers
constexpr size_t OFF_WSKT   = OFF_XB     + 2 * (size_t)XSZ;
constexpr size_t OFF_WRST   = OFF_WSKT   + 262144;
constexpr size_t OFF_WDT    = OFF_WRST   + 61440;                 // [l][j][c] float2
constexpr size_t SCRATCH_SZ = OFF_WDT + 262144;

__device__ __align__(1024) float g_scratch[SCRATCH_SZ];
__device__ unsigned g_bar;
__device__ unsigned g_cnt1[8];
__device__ unsigned g_cnt2[16];

// ---------------- PTX helpers -------------------------------------------------------
__device__ __forceinline__ uint32_t s2u(const void* p) {
    uint32_t a;
    asm("{ .reg .u64 t; cvta.to.shared.u64 t, %1; cvt.u32.u64 %0, t; }" : "=r"(a) : "l"(p));
    return a;
}
__device__ __forceinline__ void cp16(uint32_t dst, const void* src) {
    asm volatile("cp.async.cg.shared.global [%0], [%1], 16;" :: "r"(dst), "l"(src));
}
#define CP_COMMIT() asm volatile("cp.async.commit_group;" ::: "memory")

__device__ __forceinline__ void ldsm4(uint32_t* r, uint32_t a) {
    asm volatile("ldmatrix.sync.aligned.m8n8.x4.shared.b16 {%0,%1,%2,%3}, [%4];"
                 : "=r"(r[0]), "=r"(r[1]), "=r"(r[2]), "=r"(r[3]) : "r"(a));
}
__device__ __forceinline__ void ldsm4t(uint32_t* r, uint32_t a) {
    asm volatile("ldmatrix.sync.aligned.m8n8.x4.trans.shared.b16 {%0,%1,%2,%3}, [%4];"
                 : "=r"(r[0]), "=r"(r[1]), "=r"(r[2]), "=r"(r[3]) : "r"(a));
}
__device__ __forceinline__ void mma_f16(float* c, const uint32_t* a, const uint32_t* b) {
    asm volatile("mma.sync.aligned.m16n8k16.row.col.f32.f16.f16.f32 "
                 "{%0,%1,%2,%3}, {%4,%5,%6,%7}, {%8,%9}, {%0,%1,%2,%3};"
                 : "+f"(c[0]), "+f"(c[1]), "+f"(c[2]), "+f"(c[3])
                 : "r"(a[0]), "r"(a[1]), "r"(a[2]), "r"(a[3]), "r"(b[0]), "r"(b[1]));
}

__device__ __forceinline__ uint32_t off_km64(int row, int kk) {
    return (uint32_t)(row * 128 + ((kk ^ (row & 7)) << 4));
}
__device__ __forceinline__ uint32_t off_tr64(int k, int mc) {
    return (uint32_t)(k * 256 + ((mc ^ (k & 7)) << 4));
}
__device__ __forceinline__ unsigned ldacq(const unsigned* p) {
    unsigned v;
    asm volatile("ld.acquire.gpu.global.u32 %0, [%1];" : "=r"(v) : "l"(p) : "memory");
    return v;
}

// ---------------- prep mega-kernel ---------------------------------------------------
__global__ __launch_bounds__(256)
void k_prep(const float* __restrict__ features, const float* __restrict__ w_cond,
            const float* __restrict__ w_out, const float* __restrict__ w_end,
            const float* __restrict__ w_skip, const float* __restrict__ w_res,
            const float* __restrict__ w_dil)
{
    __shared__ float tile[32 * 33 * 2];
    float2* tile2 = reinterpret_cast<float2*>(tile);
    const int b = blockIdx.x, tid = threadIdx.x;
    const int x = tid & 31, y = tid >> 5;

    __half* WC = (__half*)(g_scratch + OFF_WC);
    __half* FT = (__half*)(g_scratch + OFF_FT);

    auto tr = [&](const float* ip, float* op, int R, int C, int c0, int r0) {
#pragma unroll
        for (int i = 0; i < 32; i += 8)
            tile[(y + i) * 33 + x] = ip[(size_t)(r0 + y + i) * C + c0 + x];
        __syncthreads();
#pragma unroll
        for (int i = 0; i < 32; i += 8)
            op[(size_t)(c0 + y + i) * R + r0 + x] = tile[x * 33 + y + i];
    };

    if (b < 4096) {
        int i = b * 256 + tid;
        float4 v = reinterpret_cast<const float4*>(w_cond)[i];
        __half h0 = __float2half_rn(v.x), h1 = __float2half_rn(v.y);
        __half h2 = __float2half_rn(v.z), h3 = __float2half_rn(v.w);
        uint2 vh = make_uint2(
            (uint32_t)__half_as_ushort(h0) | ((uint32_t)__half_as_ushort(h1) << 16),
            (uint32_t)__half_as_ushort(h2) | ((uint32_t)__half_as_ushort(h3) << 16));
        reinterpret_cast<uint2*>(WC)[i] = vh;
    } else if (b < 4352) {
        int t = b - 4096;
        int c0 = (t & 3) * 32, r0 = (t >> 2) * 32;
#pragma unroll
        for (int i = 0; i < 32; i += 8)
            tile[(y + i) * 33 + x] = features[(size_t)(r0 + y + i) * 128 + c0 + x];
        __syncthreads();
#pragma unroll
        for (int i = 0; i < 32; i += 8) {
            float v = tile[x * 33 + y + i];
            size_t o = (size_t)(c0 + y + i) * 2048 + r0 + x;
            FT[o] = __float2half_rn(v);
        }
    } else if (b < 4416) {
        int t = b - 4352;
        tr(w_out, g_scratch + OFF_WOT, 256, 256, (t & 7) * 32, (t >> 3) * 32);
    } else if (b < 4480) {
        int t = b - 4416;
        tr(w_end, g_scratch + OFF_WET, 256, 256, (t & 7) * 32, (t >> 3) * 32);
    } else if (b < 4736) {
        int t = b - 4480;
        int l = t >> 4, bx = t & 1, by = (t >> 1) & 7;
        tr(w_skip + (size_t)l * 16384, g_scratch + OFF_WSKT + (size_t)l * 16384,
           256, 64, bx * 32, by * 32);
    } else if (b < 4796) {
        int t = b - 4736;
        int l = t >> 2, bx = t & 1, by = (t >> 1) & 1;
        tr(w_res + (size_t)l * 4096, g_scratch + OFF_WRST + (size_t)l * 4096,
           64, 64, bx * 32, by * 32);
    } else if (b < 4924) {
        int t = b - 4796;
        int l = t >> 3, sub = t & 7;
        int r0 = (sub >> 1) * 32;               // c dim
        int c0 = (sub & 1) * 32;                // j dim
        const float2* ip2 = reinterpret_cast<const float2*>(w_dil + (size_t)l * 16384);
        float2* op2 = reinterpret_cast<float2*>(g_scratch + OFF_WDT) + (size_t)l * 8192;
#pragma unroll
        for (int i = 0; i < 32; i += 8)
            tile2[(y + i) * 33 + x] = ip2[(size_t)(r0 + y + i) * 64 + c0 + x];
        __syncthreads();
#pragma unroll
        for (int i = 0; i < 32; i += 8)
            op2[(size_t)(c0 + y + i) * 128 + r0 + x] = tile2[x * 33 + y + i];
    } else {
        if (tid < 8)  g_cnt1[tid] = 0u;
        if (tid < 16) g_cnt2[tid] = 0u;
        if (tid == 0) g_bar = 0u;
    }
}

// ---------------- GEMM core (single fp16 A and B) ------------------------------------
__device__ __forceinline__ void gemm_core(
    char* smem, uint32_t sb, int tid,
    const __half* __restrict__ A, const __half* __restrict__ B,
    int K, int bm, int bn, int mode, const float* __restrict__ bias,
    float* __restrict__ outF, __half* __restrict__ outH)
{
    const int wid = tid >> 5, lane = tid & 31;
    const int wm = (wid & 3) * 32, wn = (wid >> 2) * 32;
    const uint32_t STG = 32768;   // A 16K | B 16K

    float acc[2][4][4];
#pragma unroll
    for (int mt = 0; mt < 2; mt++)
#pragma unroll
        for (int nt = 0; nt < 4; nt++)
#pragma unroll
            for (int i = 0; i < 4; i++) acc[mt][nt][i] = 0.0f;

    const int nsteps = K >> 6;

    auto fill_ab = [&](int s, int k0) {
        uint32_t base = sb + (uint32_t)s * STG;
#pragma unroll
        for (int i = 0; i < 2; i++) {
            int idx = tid + i * 512;
            int row = idx >> 3, kk = idx & 7;
            uint32_t d = off_km64(row, kk);
            cp16(base + d,         A + (size_t)(bm + row) * K + k0 + kk * 8);
            cp16(base + 16384 + d, B + (size_t)(bn + row) * K + k0 + kk * 8);
        }
    };

    fill_ab(0, 0);  CP_COMMIT();
    fill_ab(1, 64); CP_COMMIT();

    int sc = 0;
    for (int it = 0; it < nsteps; it++) {
        int sn = sc + 1; if (sn == 3) sn = 0;
        int sf = sn + 1; if (sf == 3) sf = 0;

        if (it < nsteps - 1)
            asm volatile("cp.async.wait_group 1;" ::: "memory");
        else
            asm volatile("cp.async.wait_group 0;" ::: "memory");
        __syncthreads();

        if (it + 2 < nsteps) { fill_ab(sf, (it + 2) * 64); CP_COMMIT(); }

        uint32_t base = sb + (uint32_t)sc * STG;
#pragma unroll
        for (int s = 0; s < 4; s++) {
            const int kk0 = s * 2;
            uint32_t af[2][4];
#pragma unroll
            for (int mt = 0; mt < 2; mt++) {
                int r2 = wm + mt * 16 + (lane & 15);
                int k2 = kk0 + (lane >> 4);
                ldsm4(af[mt], base + off_km64(r2, k2));
            }
            uint32_t bh[4][2];
#pragma unroll
            for (int p = 0; p < 2; p++) {
                int r2 = wn + p * 16 + ((lane >> 4) << 3) + (lane & 7);
                int k2 = kk0 + ((lane >> 3) & 1);
                uint32_t r[4];
                ldsm4(r, base + 16384 + off_km64(r2, k2));
                bh[2 * p][0] = r[0]; bh[2 * p][1] = r[1];
                bh[2 * p + 1][0] = r[2]; bh[2 * p + 1][1] = r[3];
            }
#pragma unroll
            for (int mt = 0; mt < 2; mt++)
#pragma unroll
                for (int nt = 0; nt < 4; nt++)
                    mma_f16(acc[mt][nt], af[mt], bh[nt]);
        }
        sc = sn;
    }
    __syncthreads();

    float* sd = reinterpret_cast<float*>(smem);
#pragma unroll
    for (int mt = 0; mt < 2; mt++)
#pragma unroll
        for (int nt = 0; nt < 4; nt++) {
            int r = wm + mt * 16 + (lane >> 2);
            int c = wn + nt * 8 + (lane & 3) * 2;
            sd[r * 129 + c]           = acc[mt][nt][0];
            sd[r * 129 + c + 1]       = acc[mt][nt][1];
            sd[(r + 8) * 129 + c]     = acc[mt][nt][2];
            sd[(r + 8) * 129 + c + 1] = acc[mt][nt][3];
        }
    __syncthreads();

    if (mode == 1) {
        int mg = (tid & 31) * 4;
        int nl = tid >> 5;
        for (int n0 = 0; n0 < 128; n0 += 16) {
            int n = n0 + nl;
            uint2 vh;
            __half* hp = (__half*)&vh;
#pragma unroll
            for (int j = 0; j < 4; j++) {
                float v = sd[(mg + j) * 129 + n] + bias[bm + mg + j];
                hp[j] = __float2half_rn(v);
            }
            *reinterpret_cast<uint2*>(outH + (size_t)(bn + n) * 2048 + bm + mg) = vh;
        }
    } else {
        int mo = tid >> 7, n = tid & 127;
        int gn = bn + n;
        if (gn < T_LEN) {
            for (int m0 = 0; m0 < 128; m0 += 4) {
                int m = m0 + mo;
                outF[(size_t)(bm + m) * T_LEN + gn] = sd[m * 129 + n] + bias[bm + m];
            }
        }
    }
}

// ---------------- upsample GEMM (single fp16, 512 thr, 2 m-tiles per block) ---------
__global__ __launch_bounds__(512)
void k_gemm_up(const float* __restrict__ Af32,
               const __half* __restrict__ B,
               const float* __restrict__ bias,
               __half* __restrict__ outH)
{
    extern __shared__ char smem[];
    uint32_t sb = s2u(smem);
    const int tid = threadIdx.x;
    const int wid = tid >> 5, lane = tid & 31;
    const int Mg = 32768, K = 2048;
    const int wm = (wid & 3) * 32, wn = (wid >> 2) * 32;
    const uint32_t STG = 32768;   // A 16K | B 16K
    const int nsteps = K >> 6;

    for (int tile = 0; tile < 2; tile++) {
        const int bm = (blockIdx.x + tile * 128) * 128;

        float acc[2][4][4];
#pragma unroll
        for (int mt = 0; mt < 2; mt++)
#pragma unroll
            for (int nt = 0; nt < 4; nt++)
#pragma unroll
                for (int i = 0; i < 4; i++) acc[mt][nt][i] = 0.0f;

        float4 pre[4];

        auto ldg_pre = [&](int k0) {
#pragma unroll
            for (int i = 0; i < 4; i++) {
                int u = tid + i * 512;
                int k = u >> 5, f4 = u & 31;
                pre[i] = *reinterpret_cast<const float4*>(
                    Af32 + (size_t)(k0 + k) * Mg + bm + f4 * 4);
            }
        };
        auto sts_pre = [&](int s) {
#pragma unroll
            for (int i = 0; i < 4; i++) {
                int u = tid + i * 512;
                int k = u >> 5, f4 = u & 31;
                float4 v = pre[i];
                __half h0 = __float2half_rn(v.x), h1 = __float2half_rn(v.y);
                __half h2 = __float2half_rn(v.z), h3 = __float2half_rn(v.w);
                uint32_t hi01 = (uint32_t)__half_as_ushort(h0) |
                                ((uint32_t)__half_as_ushort(h1) << 16);
                uint32_t hi23 = (uint32_t)__half_as_ushort(h2) |
                                ((uint32_t)__half_as_ushort(h3) << 16);
                int mc = f4 >> 1, half = f4 & 1;
                uint32_t a = (uint32_t)s * STG + off_tr64(k, mc) + half * 8;
                *reinterpret_cast<uint2*>(smem + a) = make_uint2(hi01, hi23);
            }
        };
        auto fill_b = [&](int s, int k0) {
            uint32_t base = sb + (uint32_t)s * STG;
#pragma unroll
            for (int i = 0; i < 2; i++) {
                int idx = tid + i * 512;
                int row = idx >> 3, kk = idx & 7;
                uint32_t d = off_km64(row, kk);
                cp16(base + 16384 + d, B + (size_t)row * K + k0 + kk * 8);
            }
        };

        ldg_pre(0);
        sts_pre(0);
        ldg_pre(64);
        fill_b(0, 0);  CP_COMMIT();
        fill_b(1, 64); CP_COMMIT();

        int sc = 0;
        for (int it = 0; it < nsteps; it++) {
            int sn = sc + 1; if (sn == 3) sn = 0;
            int sf = sn + 1; if (sf == 3) sf = 0;

            if (it < nsteps - 1)
                asm volatile("cp.async.wait_group 1;" ::: "memory");
            else
                asm volatile("cp.async.wait_group 0;" ::: "memory");
            __syncthreads();

            if (it + 1 < nsteps) sts_pre(sn);
            if (it + 2 < nsteps) {
                ldg_pre((it + 2) * 64);
                fill_b(sf, (it + 2) * 64);
                CP_COMMIT();
            }

            uint32_t base = sb + (uint32_t)sc * STG;
#pragma unroll
            for (int s = 0; s < 4; s++) {
                const int kk0 = s * 2;
                uint32_t af[2][4];
#pragma unroll
                for (int mt = 0; mt < 2; mt++) {
                    int k  = s * 16 + ((lane >> 4) << 3) + (lane & 7);
                    int mc = ((wm + mt * 16) >> 3) + ((lane >> 3) & 1);
                    ldsm4t(af[mt], base + off_tr64(k, mc));
                }
                uint32_t bh[4][2];
#pragma unroll
                for (int p = 0; p < 2; p++) {
                    int r2 = wn + p * 16 + ((lane >> 4) << 3) + (lane & 7);
                    int k2 = kk0 + ((lane >> 3) & 1);
                    uint32_t r[4];
                    ldsm4(r, base + 16384 + off_km64(r2, k2));
                    bh[2 * p][0] = r[0]; bh[2 * p][1] = r[1];
                    bh[2 * p + 1][0] = r[2]; bh[2 * p + 1][1] = r[3];
                }
#pragma unroll
                for (int mt = 0; mt < 2; mt++)
#pragma unroll
                    for (int nt = 0; nt < 4; nt++)
                        mma_f16(acc[mt][nt], af[mt], bh[nt]);
            }
            sc = sn;
        }
        __syncthreads();

        float* sd = reinterpret_cast<float*>(smem);
#pragma unroll
        for (int mt = 0; mt < 2; mt++)
#pragma unroll
            for (int nt = 0; nt < 4; nt++) {
                int r = wm + mt * 16 + (lane >> 2);
                int c = wn + nt * 8 + (lane & 3) * 2;
                sd[r * 129 + c]           = acc[mt][nt][0];
                sd[r * 129 + c + 1]       = acc[mt][nt][1];
                sd[(r + 8) * 129 + c]     = acc[mt][nt][2];
                sd[(r + 8) * 129 + c + 1] = acc[mt][nt][3];
            }
        __syncthreads();

        int bo = bm >> 4;
        for (int u = tid; u < T_LEN; u += 512) {
            int m = u >> 3, p = u & 7;
            uint4 vh;
            __half* hp = (__half*)&vh;
#pragma unroll
            for (int ol = 0; ol < 8; ol++) {
                float v = sd[(ol * 16 + p + 8) * 129 + m] +
                          sd[(ol * 16 + p) * 129 + m + 1] + bias[bo + ol];
                hp[ol] = __float2half_rn(v);
            }
            *reinterpret_cast<uint4*>(outH + (size_t)u * 2048 + bo) = vh;
        }
        __syncthreads();
    }
}

// ---------------- fused: encode/embed + cond1 + cond2 + lock-step tail ---------------
__global__ __launch_bounds__(512)
void k_fused(const float* __restrict__ b_cond,
             const float* __restrict__ audio, const float* __restrict__ embed,
             const float* __restrict__ b_dil_all, const float* __restrict__ b_res_all,
             const float* __restrict__ b_skip_all,
             float* __restrict__ out, int write_q)
{
    extern __shared__ char smem[];
    uint32_t sb = s2u(smem);
    const int tid = threadIdx.x;
    const int b = blockIdx.x;
    const int t0 = b * TB;
    float* XB = g_scratch + OFF_XB;

    // ---- phase 0: encode + embed ----
    if (b < NTAIL) {
        int j = tid >> 3, tt = tid & 7;
        int t = t0 + tt;
        float x = audio[t];
        float xc = fminf(1.0f, fmaxf(-1.0f, x));
        float s  = (xc > 0.0f) ? 1.0f : ((xc < 0.0f) ? -1.0f : 0.0f);
        float num = log1pf(__fmul_rn(255.0f, fabsf(xc)));
        float den = log1pf(255.0f);
        float m = __fdiv_rn(__fmul_rn(s, num), den);
        float v = __fadd_rn(__fmul_rn(__fmul_rn(__fadd_rn(m, 1.0f), 0.5f), 255.0f), 0.5f);
        v = fminf(255.0f, fmaxf(0.0f, v));
        int q = (int)v;
        if (write_q && tid < TB) out[(size_t)256 * T_LEN + t] = (float)q;
        XB[(size_t)j * T_LEN + t0 + tt] = embed[q * 64 + j];
        __threadfence();
        __syncthreads();
        if (tid == 0) atomicAdd(&g_bar, 1u);
    }

    __half* WC = (__half*)(g_scratch + OFF_WC);
    __half* BR = (__half*)(g_scratch + OFF_BR);
    __half* B2 = (__half*)(g_scratch + OFF_B2);

    const int bm = (b >> 3) * 128, bn = (b & 7) * 128;

    // ---- phase 1: cond GEMM #1 tile ----
    gemm_core(smem, sb, tid, WC, BR, 2048, bm, bn, 1, b_cond, nullptr, B2);
    __syncthreads();
    __threadfence();
    if (tid == 0) {
        atomicAdd(&g_cnt1[b & 7], 1u);
        while (ldacq(&g_cnt1[b & 7]) < 16u) {}
    }
    __syncthreads();

    // ---- phase 2: cond GEMM #2 tile ----
    gemm_core(smem, sb, tid, WC, B2, 2048, bm, bn, 2, b_cond,
              g_scratch + OFF_CACTS, nullptr);
    __syncthreads();
    __threadfence();
    if (tid == 0) atomicAdd(&g_cnt2[b >> 3], 1u);

    if (b >= NTAIL) return;

    // ---- phase 3: lock-step tail ----
    float*  smf = reinterpret_cast<float*>(smem);
    float2* WD2 = reinterpret_cast<float2*>(smf);
    float*  WSK = smf + 16384;
    float*  WRS = smf + 32768;
    float*  XS0 = smf + 36864;
    float*  XS1 = XS0 + 512;
    float*  IA  = XS1 + 512;
    float*  ACT = IA + 512;
    float*  HS  = ACT + 512;
    float*  HS2 = HS + 2048;

    __syncthreads();   // smem repurpose safety

    float s_acc[4];
#pragma unroll
    for (int i = 0; i < 4; i++) s_acc[i] = 0.0f;

    const int c   = tid & 127;
    const int th  = tid >> 7;       // 0..3, 2 timesteps each
    const int row = tid & 255;
    const int part = tid >> 8;      // 0..1, 4 timesteps each

    for (int layer = 0; layer < 16; layer++) {
        const int d = 1 << (layer & 7);
        const float* xin  = XB + (size_t)(layer & 1) * XSZ;
        float*       xout = XB + (size_t)((layer + 1) & 1) * XSZ;
        const float* cond = g_scratch + OFF_CACTS + (size_t)layer * 128 * T_LEN;
        const char*  wdl  = (const char*)(g_scratch + OFF_WDT + (size_t)layer * 16384);
        const char*  wskl = (const char*)(g_scratch + OFF_WSKT + (size_t)layer * 16384);
        const char*  wrsl = (const char*)(g_scratch + OFF_WRST + (size_t)layer * 4096);

        __syncthreads();   // all prior-layer WSK/WRS reads complete before restage

        // stage all layer weights via cp.async (overlaps barrier wait)
#pragma unroll
        for (int i = 0; i < 8; i++) {
            int ch = tid + i * 512;
            cp16(sb + ch * 16, wdl + ch * 16);
            cp16(sb + 65536 + ch * 16, wskl + ch * 16);
        }
#pragma unroll
        for (int i = 0; i < 2; i++) {
            int ch = tid + i * 512;
            cp16(sb + 131072 + ch * 16, wrsl + ch * 16);
        }
        CP_COMMIT();

        if (tid == 0) {
            unsigned tgt = (unsigned)NTAIL * (unsigned)(layer + 1);
            while (ldacq(&g_bar) < tgt) {}
            while (ldacq(&g_cnt2[layer]) < 8u) {}
        }
        __syncthreads();

        // stage x windows
        {
            int j = tid >> 3, tt = tid & 7;
            int ta = t0 - d + tt;
            XS0[tid] = (ta >= 0) ? __ldcg(&xin[(size_t)j * T_LEN + ta]) : 0.0f;
            XS1[tid] = __ldcg(&xin[(size_t)j * T_LEN + t0 + tt]);
        }
        float bd  = b_dil_all[layer * 128 + c];
        float cv0 = cond[(size_t)c * T_LEN + t0 + th * 2];
        float cv1 = cond[(size_t)c * T_LEN + t0 + th * 2 + 1];
        asm volatile("cp.async.wait_group 0;" ::: "memory");
        __syncthreads();

        // dilated conv: 2 timesteps per thread
        float a0 = 0.0f, a1 = 0.0f;
#pragma unroll 16
        for (int j = 0; j < 64; j++) {
            float2 w  = WD2[j * 128 + c];
            float2 x0 = *reinterpret_cast<const float2*>(&XS0[j * TB + th * 2]);
            float2 x1 = *reinterpret_cast<const float2*>(&XS1[j * TB + th * 2]);
            a0 += w.x * x0.x + w.y * x1.x;
            a1 += w.x * x0.y + w.y * x1.y;
        }
        a0 += bd + cv0;
        a1 += bd + cv1;

        __syncthreads();
        if (c >= 64) {
            IA[(c - 64) * TB + th * 2]     = a0;
            IA[(c - 64) * TB + th * 2 + 1] = a1;
        }
        __syncthreads();
        if (c < 64) {
            float g0 = IA[c * TB + th * 2];
            float g1 = IA[c * TB + th * 2 + 1];
            ACT[c * TB + th * 2]     = tanhf(a0) * (1.0f / (1.0f + expf(-g0)));
            ACT[c * TB + th * 2 + 1] = tanhf(a1) * (1.0f / (1.0f + expf(-g1)));
        }
        __syncthreads();

        // residual (1 timestep per thread), then arrive
        if (layer < 15) {
            int c2 = tid & 63, qq = tid >> 6;
            float r = 0.0f;
#pragma unroll 8
            for (int k = 0; k < 64; k++)
                r += WRS[k * 64 + c2] * ACT[k * TB + qq];
            float br = b_res_all[layer * 64 + c2];
            int t = t0 + qq;
            xout[(size_t)c2 * T_LEN + t] = __ldcg(&xin[(size_t)c2 * T_LEN + t]) + r + br;
            __threadfence();
            __syncthreads();
            if (tid == 0) atomicAdd(&g_bar, 1u);
        }

        // skip accumulation (4 timesteps per thread) from smem weights
        {
#pragma unroll 8
            for (int k = 0; k < 64; k++) {
                float w = WSK[k * 256 + row];
                float4 a = *reinterpret_cast<const float4*>(&ACT[k * TB + part * 4]);
                s_acc[0] += w * a.x; s_acc[1] += w * a.y;
                s_acc[2] += w * a.z; s_acc[3] += w * a.w;
            }
            float bs = b_skip_all[layer * 256 + row];
#pragma unroll
            for (int i = 0; i < 4; i++) s_acc[i] += bs;
        }
    }

    // ---- heads ----
    {
        __syncthreads();
#pragma unroll
        for (int i = 0; i < 4; i++)
            HS[row * TB + part * 4 + i] = fmaxf(s_acc[i], 0.0f);
        __syncthreads();

        const float* wo = g_scratch + OFF_WOT;
        float h[4] = {0.0f, 0.0f, 0.0f, 0.0f};
        for (int cc = 0; cc < 256; cc++) {
            float w = wo[cc * 256 + row];
            float4 v = *reinterpret_cast<const float4*>(&HS[cc * TB + part * 4]);
            h[0] += w * v.x; h[1] += w * v.y; h[2] += w * v.z; h[3] += w * v.w;
        }
#pragma unroll
        for (int i = 0; i < 4; i++)
            HS2[row * TB + part * 4 + i] = fmaxf(h[i], 0.0f);
        __syncthreads();

        const float* we = g_scratch + OFF_WET;
        float h2[4] = {0.0f, 0.0f, 0.0f, 0.0f};
        for (int cc = 0; cc < 256; cc++) {
            float w = we[cc * 256 + row];
            float4 v = *reinterpret_cast<const float4*>(&HS2[cc * TB + part * 4]);
            h2[0] += w * v.x; h2[1] += w * v.y; h2[2] += w * v.z; h2[3] += w * v.w;
        }

        if (b == 0 && part == 0) out[(size_t)row * T_LEN] = 0.0f;
#pragma unroll
        for (int i = 0; i < 4; i++) {
            int t = t0 + part * 4 + i;
            if (t + 1 < T_LEN) out[(size_t)row * T_LEN + t + 1] = h2[i];
        }
    }
}

// ---------------- launch -------------------------------------------------------------
extern "C" void kernel_launch(void* const* d_in, const int* in_sizes, int n_in,
                              void* d_out, int out_size)
{
    const float* features = (const float*)d_in[0];
    const float* audio    = (const float*)d_in[1];
    const float* w_up     = (const float*)d_in[2];
    const float* b_up     = (const float*)d_in[3];
    const float* w_cond   = (const float*)d_in[4];
    const float* b_cond   = (const float*)d_in[5];
    const float* embed    = (const float*)d_in[6];
    const float* w_dil    = (const float*)d_in[7];
    const float* b_dil    = (const float*)d_in[8];
    const float* w_res    = (const float*)d_in[9];
    const float* b_res    = (const float*)d_in[10];
    const float* w_skip   = (const float*)d_in[11];
    const float* b_skip   = (const float*)d_in[12];
    const float* w_out    = (const float*)d_in[13];
    const float* w_end    = (const float*)d_in[14];
    float* out = (float*)d_out;

    float* scr = nullptr;
    cudaGetSymbolAddress((void**)&scr, g_scratch);

    __half* FT = (__half*)(scr + OFF_FT);
    __half* BR = (__half*)(scr + OFF_BR);

    cudaFuncSetAttribute(k_gemm_up, cudaFuncAttributeMaxDynamicSharedMemorySize, 196608);
    cudaFuncSetAttribute(k_fused,   cudaFuncAttributeMaxDynamicSharedMemorySize, 196608);

    int write_q = (out_size >= 256 * T_LEN + T_LEN) ? 1 : 0;

    // [1] prep
    k_prep<<<4925, 256>>>(features, w_cond, w_out, w_end, w_skip, w_res, w_dil);
    // [2] upsample GEMM (single fp16, 512 thr, 2 tiles/block)
    k_gemm_up<<<128, 512, 196608>>>(w_up, FT, b_up, BR);
    // [3] fused encode/embed + cond1 + cond2 + tail
    k_fused<<<128, 512, 196608>>>(b_cond, audio, embed, b_dil, b_res, b_skip,
                                  out, write_q);
}